// round 2
// baseline (speedup 1.0000x reference)
#include <cuda_runtime.h>
#include <math.h>
#include <stdint.h>

// Problem constants
#define BATCH 16
#define SEQ   1024
#define CDIM  512
#define HDIM  64         // head dim
#define SCALE 0.125f     // 1/sqrt(64)

// ---------------------------------------------------------------------------
// Scratch (device globals — no allocations allowed)
// ---------------------------------------------------------------------------
__device__ float g_xp    [BATCH*SEQ*CDIM];     // x + pos_emb
__device__ float g_qkv_h [BATCH*SEQ*768];      // hifi qkv
__device__ float g_ql    [BATCH*SEQ*256];      // lofi q
__device__ float g_kvl   [BATCH*SEQ*512];      // lofi kv
__device__ float g_hifi_o[BATCH*SEQ*256];
__device__ float g_lofi_o[BATCH*SEQ*256];
__device__ float g_y     [BATCH*SEQ*512];      // concat(hifi_proj, lofi_proj)
__device__ float g_qkv_m [BATCH*SEQ*1536];     // mha qkv
__device__ float g_mha_o [BATCH*SEQ*512];

// ---------------------------------------------------------------------------
// x + pos_emb (pos broadcast over batch)
// ---------------------------------------------------------------------------
__global__ __launch_bounds__(256) void add_pos_kernel(
    const float* __restrict__ x, const float* __restrict__ pos, float* __restrict__ xp)
{
    const int per_b4 = SEQ*CDIM/4;  // 131072
    int i = blockIdx.x * blockDim.x + threadIdx.x;   // float4 index, grid covers all
    float4 a = reinterpret_cast<const float4*>(x)[i];
    float4 p = reinterpret_cast<const float4*>(pos)[i % per_b4];
    a.x += p.x; a.y += p.y; a.z += p.z; a.w += p.w;
    reinterpret_cast<float4*>(xp)[i] = a;
}

// ---------------------------------------------------------------------------
// SGEMM: C[M,N] = A[M,K] @ W[K,N] (+bias). Row-major everywhere.
// 128x128 block, BK=8, 256 threads, 8x8 per-thread register tile.
// Requires: M%128==0, N%128==0, K%8==0, lda/ldc multiples of 4.
// ---------------------------------------------------------------------------
__global__ __launch_bounds__(256) void sgemm_kernel(
    const float* __restrict__ A, const float* __restrict__ W,
    const float* __restrict__ bias, float* __restrict__ C,
    int M, int N, int K, int lda, int ldc)
{
    __shared__ float As[8][128];   // transposed A tile
    __shared__ float Bs[8][128];

    const int tid  = threadIdx.x;
    const int row0 = blockIdx.y * 128;
    const int col0 = blockIdx.x * 128;
    const int trow = tid >> 4;           // 0..15
    const int tcol = tid & 15;           // 0..15
    const int aRow = tid >> 1;           // 0..127
    const int aCol = (tid & 1) * 4;      // 0 or 4
    const int bRow = tid >> 5;           // 0..7
    const int bCol = (tid & 31) * 4;     // 0..124

    const float* Ab = A + (size_t)row0 * lda;
    const float* Wb = W + col0;

    float acc[8][8];
    #pragma unroll
    for (int i = 0; i < 8; i++)
        #pragma unroll
        for (int j = 0; j < 8; j++) acc[i][j] = 0.f;

    for (int k0 = 0; k0 < K; k0 += 8) {
        float4 a4 = *reinterpret_cast<const float4*>(Ab + (size_t)aRow * lda + k0 + aCol);
        As[aCol+0][aRow] = a4.x;
        As[aCol+1][aRow] = a4.y;
        As[aCol+2][aRow] = a4.z;
        As[aCol+3][aRow] = a4.w;
        float4 b4 = *reinterpret_cast<const float4*>(Wb + (size_t)(k0 + bRow) * N + bCol);
        *reinterpret_cast<float4*>(&Bs[bRow][bCol]) = b4;
        __syncthreads();

        #pragma unroll
        for (int kk = 0; kk < 8; kk++) {
            float regM[8], regN[8];
            *reinterpret_cast<float4*>(&regM[0]) = *reinterpret_cast<float4*>(&As[kk][trow*8]);
            *reinterpret_cast<float4*>(&regM[4]) = *reinterpret_cast<float4*>(&As[kk][trow*8+4]);
            *reinterpret_cast<float4*>(&regN[0]) = *reinterpret_cast<float4*>(&Bs[kk][tcol*8]);
            *reinterpret_cast<float4*>(&regN[4]) = *reinterpret_cast<float4*>(&Bs[kk][tcol*8+4]);
            #pragma unroll
            for (int i = 0; i < 8; i++)
                #pragma unroll
                for (int j = 0; j < 8; j++)
                    acc[i][j] += regM[i] * regN[j];
        }
        __syncthreads();
    }

    #pragma unroll
    for (int i = 0; i < 8; i++) {
        size_t r = (size_t)(row0 + trow*8 + i);
        float* Crow = C + r * ldc + col0 + tcol*8;
        #pragma unroll
        for (int j = 0; j < 8; j++) {
            float v = acc[i][j];
            if (bias) v += bias[col0 + tcol*8 + j];
            Crow[j] = v;
        }
    }
}

// ---------------------------------------------------------------------------
// Hifi: 2x2 window attention. One warp per (b, window, head).
// qkv layout: g_qkv_h[(b*SEQ+n)*768 + {0,256,512} + head*64 + d]
// out: g_hifi_o[(b*SEQ+n)*256 + head*64 + d]
// ---------------------------------------------------------------------------
__global__ __launch_bounds__(128) void hifi_attn_kernel(
    const float* __restrict__ qkv, float* __restrict__ outp)
{
    const int warp = threadIdx.x >> 5;
    const int lane = threadIdx.x & 31;
    const int unit = blockIdx.x * 4 + warp;   // 0..16383
    const int head = unit & 3;
    const int g    = (unit >> 2) & 255;
    const int b    = unit >> 10;
    const int gi   = g >> 4, gj = g & 15;

    int n[4];
    #pragma unroll
    for (int t = 0; t < 4; t++)
        n[t] = (gi*2 + (t>>1)) * 32 + gj*2 + (t&1);

    float q[4][2], k[4][2], v[4][2];
    #pragma unroll
    for (int t = 0; t < 4; t++) {
        const float* p = qkv + (size_t)(b*SEQ + n[t]) * 768 + head*64;
        q[t][0] = p[lane];        q[t][1] = p[lane+32];
        k[t][0] = p[256+lane];    k[t][1] = p[256+lane+32];
        v[t][0] = p[512+lane];    v[t][1] = p[512+lane+32];
    }

    float s[4][4];
    #pragma unroll
    for (int t = 0; t < 4; t++)
        #pragma unroll
        for (int u = 0; u < 4; u++)
            s[t][u] = q[t][0]*k[u][0] + q[t][1]*k[u][1];

    #pragma unroll
    for (int off = 16; off >= 1; off >>= 1)
        #pragma unroll
        for (int t = 0; t < 4; t++)
            #pragma unroll
            for (int u = 0; u < 4; u++)
                s[t][u] += __shfl_xor_sync(0xffffffffu, s[t][u], off);

    #pragma unroll
    for (int t = 0; t < 4; t++) {
        float s0 = s[t][0]*SCALE, s1 = s[t][1]*SCALE, s2 = s[t][2]*SCALE, s3 = s[t][3]*SCALE;
        float mx = fmaxf(fmaxf(s0, s1), fmaxf(s2, s3));
        float e0 = __expf(s0-mx), e1 = __expf(s1-mx), e2 = __expf(s2-mx), e3 = __expf(s3-mx);
        float inv = 1.f / (e0+e1+e2+e3);
        e0 *= inv; e1 *= inv; e2 *= inv; e3 *= inv;
        float o0 = e0*v[0][0] + e1*v[1][0] + e2*v[2][0] + e3*v[3][0];
        float o1 = e0*v[0][1] + e1*v[1][1] + e2*v[2][1] + e3*v[3][1];
        float* op = outp + (size_t)(b*SEQ + n[t]) * 256 + head*64;
        op[lane]    = o0;
        op[lane+32] = o1;
    }
}

// ---------------------------------------------------------------------------
// Flash attention, fp32, head_dim=64, 64x64 tiles, 256 threads.
// Thread (ty,tx): q-rows ty*4..+3; for S: k-cols tx*4..+3; for O: dims tx*4..+3.
// Dynamic smem: Qs, Ks, VsT, Ps — each [64][68].
// Scale folded into Q load.
// ---------------------------------------------------------------------------
#define FP 68
#define FA_SMEM (4 * 64 * FP * (int)sizeof(float))

extern __shared__ float fa_smem[];

__global__ __launch_bounds__(256) void flash_kernel(
    const float* __restrict__ Qp, const float* __restrict__ Kp,
    const float* __restrict__ Vp, float* __restrict__ Op,
    int q_rs, int k_rs, int v_rs, int o_rs, int seq)
{
    float* Qs  = fa_smem;
    float* Ks  = Qs  + 64*FP;
    float* VsT = Ks  + 64*FP;
    float* Ps  = VsT + 64*FP;

    const int b = blockIdx.z, head = blockIdx.y, qt = blockIdx.x;
    const size_t bo = (size_t)b * seq;
    const float* qb = Qp + (bo + qt*64) * q_rs + head*64;
    const float* kb = Kp + bo * k_rs + head*64;
    const float* vb = Vp + bo * v_rs + head*64;
    float* ob       = Op + (bo + qt*64) * o_rs + head*64;

    const int tid = threadIdx.x;
    const int ty = tid >> 4, tx = tid & 15;
    const int qr0 = ty*4, kr0 = tx*4, d0 = tx*4;

    // load Q tile (scale folded in)
    for (int i = tid; i < 4096; i += 256) {
        int r = i >> 6, c = i & 63;
        Qs[r*FP + c] = qb[(size_t)r * q_rs + c] * SCALE;
    }

    float m[4], l[4], o[4][4];
    #pragma unroll
    for (int i = 0; i < 4; i++) {
        m[i] = -1e30f; l[i] = 0.f;
        #pragma unroll
        for (int d = 0; d < 4; d++) o[i][d] = 0.f;
    }

    const int ntiles = seq >> 6;
    for (int kt = 0; kt < ntiles; kt++) {
        __syncthreads();   // prev PV done (and Q load visible on first iter)
        const float* kbt = kb + (size_t)kt * 64 * k_rs;
        const float* vbt = vb + (size_t)kt * 64 * v_rs;
        for (int i = tid; i < 4096; i += 256) {
            int r = i >> 6, c = i & 63;
            Ks [r*FP + c] = kbt[(size_t)r * k_rs + c];
            VsT[c*FP + r] = vbt[(size_t)r * v_rs + c];
        }
        __syncthreads();

        // S = Q K^T  (4x4 per thread)
        float s[4][4];
        #pragma unroll
        for (int i = 0; i < 4; i++)
            #pragma unroll
            for (int j = 0; j < 4; j++) s[i][j] = 0.f;

        for (int k = 0; k < 64; k += 4) {
            float4 qv[4], kv[4];
            #pragma unroll
            for (int i = 0; i < 4; i++)
                qv[i] = *reinterpret_cast<float4*>(&Qs[(qr0+i)*FP + k]);
            #pragma unroll
            for (int j = 0; j < 4; j++)
                kv[j] = *reinterpret_cast<float4*>(&Ks[(kr0+j)*FP + k]);
            #pragma unroll
            for (int i = 0; i < 4; i++)
                #pragma unroll
                for (int j = 0; j < 4; j++)
                    s[i][j] += qv[i].x*kv[j].x + qv[i].y*kv[j].y
                             + qv[i].z*kv[j].z + qv[i].w*kv[j].w;
        }

        // online softmax (row groups = 16 lanes sharing ty)
        #pragma unroll
        for (int i = 0; i < 4; i++) {
            float mx = fmaxf(fmaxf(s[i][0], s[i][1]), fmaxf(s[i][2], s[i][3]));
            #pragma unroll
            for (int off = 8; off >= 1; off >>= 1)
                mx = fmaxf(mx, __shfl_xor_sync(0xffffffffu, mx, off));
            float mnew = fmaxf(m[i], mx);
            float corr = __expf(m[i] - mnew);
            float rs = 0.f;
            #pragma unroll
            for (int j = 0; j < 4; j++) {
                float p = __expf(s[i][j] - mnew);
                Ps[(qr0+i)*FP + kr0 + j] = p;
                rs += p;
            }
            #pragma unroll
            for (int off = 8; off >= 1; off >>= 1)
                rs += __shfl_xor_sync(0xffffffffu, rs, off);
            l[i] = l[i] * corr + rs;
            m[i] = mnew;
            #pragma unroll
            for (int d = 0; d < 4; d++) o[i][d] *= corr;
        }
        __syncthreads();

        // O += P @ V
        for (int k = 0; k < 64; k += 4) {
            float4 pv[4], vv[4];
            #pragma unroll
            for (int i = 0; i < 4; i++)
                pv[i] = *reinterpret_cast<float4*>(&Ps[(qr0+i)*FP + k]);
            #pragma unroll
            for (int d = 0; d < 4; d++)
                vv[d] = *reinterpret_cast<float4*>(&VsT[(d0+d)*FP + k]);
            #pragma unroll
            for (int i = 0; i < 4; i++)
                #pragma unroll
                for (int d = 0; d < 4; d++)
                    o[i][d] += pv[i].x*vv[d].x + pv[i].y*vv[d].y
                             + pv[i].z*vv[d].z + pv[i].w*vv[d].w;
        }
    }

    #pragma unroll
    for (int i = 0; i < 4; i++) {
        float inv = 1.f / l[i];
        float4 res = make_float4(o[i][0]*inv, o[i][1]*inv, o[i][2]*inv, o[i][3]*inv);
        *reinterpret_cast<float4*>(&ob[(size_t)(qr0+i) * o_rs + d0]) = res;
    }
}

// ---------------------------------------------------------------------------
// Launch
// ---------------------------------------------------------------------------
extern "C" void kernel_launch(void* const* d_in, const int* in_sizes, int n_in,
                              void* d_out, int out_size)
{
    const float* x         = (const float*)d_in[0];
    const float* pos_emb   = (const float*)d_in[1];
    const float* l_q_w     = (const float*)d_in[2];
    const float* l_kv_w    = (const float*)d_in[3];
    const float* l_proj_w  = (const float*)d_in[4];
    const float* l_proj_b  = (const float*)d_in[5];
    const float* h_qkv_w   = (const float*)d_in[6];
    const float* h_proj_w  = (const float*)d_in[7];
    const float* h_proj_b  = (const float*)d_in[8];
    const float* in_proj_w = (const float*)d_in[9];
    const float* in_proj_b = (const float*)d_in[10];
    const float* out_proj_w= (const float*)d_in[11];
    const float* out_proj_b= (const float*)d_in[12];
    float* out = (float*)d_out;

    float *xp, *qkvh, *ql, *kvl, *hifio, *lofio, *y, *qkvm, *mhao;
    cudaGetSymbolAddress((void**)&xp,    g_xp);
    cudaGetSymbolAddress((void**)&qkvh,  g_qkv_h);
    cudaGetSymbolAddress((void**)&ql,    g_ql);
    cudaGetSymbolAddress((void**)&kvl,   g_kvl);
    cudaGetSymbolAddress((void**)&hifio, g_hifi_o);
    cudaGetSymbolAddress((void**)&lofio, g_lofi_o);
    cudaGetSymbolAddress((void**)&y,     g_y);
    cudaGetSymbolAddress((void**)&qkvm,  g_qkv_m);
    cudaGetSymbolAddress((void**)&mhao,  g_mha_o);

    cudaFuncSetAttribute(flash_kernel, cudaFuncAttributeMaxDynamicSharedMemorySize, FA_SMEM);

    const int M = BATCH * SEQ;   // 16384

    // 1. positional encoding
    add_pos_kernel<<<(BATCH*SEQ*CDIM/4 + 255)/256, 256>>>(x, pos_emb, xp);

    // 2. projections off xp
    sgemm_kernel<<<dim3(768/128,  M/128), 256>>>(xp, h_qkv_w, nullptr, qkvh, M, 768, 512, 512, 768);
    sgemm_kernel<<<dim3(256/128,  M/128), 256>>>(xp, l_q_w,   nullptr, ql,   M, 256, 512, 512, 256);
    sgemm_kernel<<<dim3(512/128,  M/128), 256>>>(xp, l_kv_w,  nullptr, kvl,  M, 512, 512, 512, 512);

    // 3. attention branches
    hifi_attn_kernel<<<4096, 128>>>(qkvh, hifio);
    flash_kernel<<<dim3(SEQ/64, 4, BATCH), 256, FA_SMEM>>>(
        ql, kvl, kvl + 256, lofio, 256, 512, 512, 256, SEQ);

    // 4. branch projections into concat buffer y
    sgemm_kernel<<<dim3(256/128,  M/128), 256>>>(hifio, h_proj_w, h_proj_b, y,       M, 256, 256, 256, 512);
    sgemm_kernel<<<dim3(256/128,  M/128), 256>>>(lofio, l_proj_w, l_proj_b, y + 256, M, 256, 256, 256, 512);

    // 5. final MHA
    sgemm_kernel<<<dim3(1536/128, M/128), 256>>>(y, in_proj_w, in_proj_b, qkvm, M, 1536, 512, 512, 1536);
    flash_kernel<<<dim3(SEQ/64, 8, BATCH), 256, FA_SMEM>>>(
        qkvm, qkvm + 512, qkvm + 1024, mhao, 1536, 1536, 1536, 512, SEQ);
    sgemm_kernel<<<dim3(512/128,  M/128), 256>>>(mhao, out_proj_w, out_proj_b, out, M, 512, 512, 512, 512);
}

// round 4
// speedup vs baseline: 4.8248x; 4.8248x over previous
#include <cuda_runtime.h>
#include <cuda_bf16.h>
#include <math.h>
#include <stdint.h>

#define BATCH 16
#define SEQ   1024
#define CDIM  512
#define SCALE 0.125f
#define MTOT  (BATCH*SEQ)

// ---------------- scratch ----------------
__device__ float         g_qkv_h[MTOT*768];                     // hifi qkv (fp32)
__device__ __nv_bfloat16 g_ql_h [MTOT*256],  g_ql_l [MTOT*256];
__device__ __nv_bfloat16 g_kvl_h[MTOT*512],  g_kvl_l[MTOT*512];
__device__ __nv_bfloat16 g_qm_h [MTOT*1536], g_qm_l [MTOT*1536];
__device__ __nv_bfloat16 g_xp_h [MTOT*CDIM], g_xp_l [MTOT*CDIM];
__device__ __nv_bfloat16 g_hifi_h[MTOT*256], g_hifi_l[MTOT*256];
__device__ __nv_bfloat16 g_lofi_h[MTOT*256], g_lofi_l[MTOT*256];
__device__ __nv_bfloat16 g_y_h  [MTOT*512],  g_y_l  [MTOT*512];
__device__ __nv_bfloat16 g_mha_h[MTOT*512],  g_mha_l[MTOT*512];
__device__ __nv_bfloat16 g_w0h[768*512],  g_w0l[768*512];
__device__ __nv_bfloat16 g_w1h[256*512],  g_w1l[256*512];
__device__ __nv_bfloat16 g_w2h[512*512],  g_w2l[512*512];
__device__ __nv_bfloat16 g_w3h[256*256],  g_w3l[256*256];
__device__ __nv_bfloat16 g_w4h[256*256],  g_w4l[256*256];
__device__ __nv_bfloat16 g_w5h[1536*512], g_w5l[1536*512];
__device__ __nv_bfloat16 g_w6h[512*512],  g_w6l[512*512];

// ---------------- helpers ----------------
__device__ __forceinline__ uint32_t s2u(const void* p) {
    return (uint32_t)__cvta_generic_to_shared(p);
}
#define SWZ(o) ((o) ^ (((o) >> 3) & 0x70))

__device__ __forceinline__ void cp16(uint32_t smem, const void* g) {
    asm volatile("cp.async.cg.shared.global [%0], [%1], 16;"
                 :: "r"(smem), "l"(__cvta_generic_to_global(g)));
}
#define CP_COMMIT() asm volatile("cp.async.commit_group;" ::: "memory")
#define CP_WAIT(n)  asm volatile("cp.async.wait_group %0;" :: "n"(n) : "memory")

__device__ __forceinline__ void ldsm4(uint32_t& r0, uint32_t& r1, uint32_t& r2, uint32_t& r3,
                                      uint32_t a) {
    asm volatile("ldmatrix.sync.aligned.m8n8.x4.shared.b16 {%0,%1,%2,%3}, [%4];"
                 : "=r"(r0), "=r"(r1), "=r"(r2), "=r"(r3) : "r"(a));
}
__device__ __forceinline__ void ldsm4t(uint32_t& r0, uint32_t& r1, uint32_t& r2, uint32_t& r3,
                                       uint32_t a) {
    asm volatile("ldmatrix.sync.aligned.m8n8.x4.trans.shared.b16 {%0,%1,%2,%3}, [%4];"
                 : "=r"(r0), "=r"(r1), "=r"(r2), "=r"(r3) : "r"(a));
}
__device__ __forceinline__ void mma_bf16(float* d, const uint32_t* a, const uint32_t* b) {
    asm volatile("mma.sync.aligned.m16n8k16.row.col.f32.bf16.bf16.f32 "
                 "{%0,%1,%2,%3}, {%4,%5,%6,%7}, {%8,%9}, {%0,%1,%2,%3};"
                 : "+f"(d[0]), "+f"(d[1]), "+f"(d[2]), "+f"(d[3])
                 : "r"(a[0]), "r"(a[1]), "r"(a[2]), "r"(a[3]), "r"(b[0]), "r"(b[1]));
}

__device__ __forceinline__ void split2(float x, __nv_bfloat16& h, __nv_bfloat16& l) {
    h = __float2bfloat16_rn(x);
    l = __float2bfloat16_rn(x - __bfloat162float(h));
}
__device__ __forceinline__ void split_pack(float x, float y, uint32_t& hi, uint32_t& lo) {
    __nv_bfloat162 h2, l2;
    split2(x, h2.x, l2.x);
    split2(y, h2.y, l2.y);
    hi = *reinterpret_cast<uint32_t*>(&h2);
    lo = *reinterpret_cast<uint32_t*>(&l2);
}

// ---------------- x + pos -> hi/lo split ----------------
__global__ __launch_bounds__(256) void add_pos_split_kernel(
    const float* __restrict__ x, const float* __restrict__ pos,
    __nv_bfloat16* __restrict__ oh, __nv_bfloat16* __restrict__ ol)
{
    const int per_b4 = SEQ*CDIM/4;
    int i = blockIdx.x * blockDim.x + threadIdx.x;
    float4 a = reinterpret_cast<const float4*>(x)[i];
    float4 p = reinterpret_cast<const float4*>(pos)[i % per_b4];
    __nv_bfloat162 h01, h23, l01, l23;
    split2(a.x+p.x, h01.x, l01.x); split2(a.y+p.y, h01.y, l01.y);
    split2(a.z+p.z, h23.x, l23.x); split2(a.w+p.w, h23.y, l23.y);
    *reinterpret_cast<__nv_bfloat162*>(&oh[i*4])   = h01;
    *reinterpret_cast<__nv_bfloat162*>(&oh[i*4+2]) = h23;
    *reinterpret_cast<__nv_bfloat162*>(&ol[i*4])   = l01;
    *reinterpret_cast<__nv_bfloat162*>(&ol[i*4+2]) = l23;
}

// ---------------- weight transpose + split: W[K][N] -> T[N][K] ----------------
__global__ __launch_bounds__(256) void wsplit_kernel(
    const float* __restrict__ W, __nv_bfloat16* __restrict__ Th,
    __nv_bfloat16* __restrict__ Tl, int K, int N)
{
    __shared__ float ts[32][33];
    const int n0 = blockIdx.x*32, k0 = blockIdx.y*32;
    const int x = threadIdx.x, y = threadIdx.y;
    #pragma unroll
    for (int r = 0; r < 4; r++)
        ts[y + r*8][x] = W[(size_t)(k0 + y + r*8)*N + n0 + x];
    __syncthreads();
    #pragma unroll
    for (int r = 0; r < 4; r++) {
        __nv_bfloat16 h, l;
        split2(ts[x][y + r*8], h, l);
        size_t o = (size_t)(n0 + y + r*8)*K + k0 + x;
        Th[o] = h; Tl[o] = l;
    }
}

// ---------------- HMMA split-bf16 GEMM ----------------
// C[M,N] = (Ah+Al)[M,K] @ (Bh+Bl)[N,K]^T + bias; out fp32 (Cf) or split (Ch/Cl)
// BM=BN=128, BK=64, 256 threads (8 warps, 4x2), 2-stage cp.async.
#define GSTG 65536
#define GEMM_SMEM (1024 + 2*GSTG)

__global__ __launch_bounds__(256, 1) void gemm_mma_kernel(
    const __nv_bfloat16* __restrict__ Ah, const __nv_bfloat16* __restrict__ Al,
    const __nv_bfloat16* __restrict__ Bh, const __nv_bfloat16* __restrict__ Bl,
    const float* __restrict__ bias, float* __restrict__ Cf,
    __nv_bfloat16* __restrict__ Ch, __nv_bfloat16* __restrict__ Cl,
    int N, int K, int ldc)
{
    extern __shared__ char smem[];
    const uint32_t sb = s2u(smem);
    const uint32_t db = (sb + 1023u) & ~1023u;
    const int tid = threadIdx.x, wid = tid >> 5, lane = tid & 31;
    const int m0 = blockIdx.y*128, n0 = blockIdx.x*128;
    const int wm = (wid & 3)*32, wn = (wid >> 2)*64;

    float acc[2][8][4];
    #pragma unroll
    for (int mt = 0; mt < 2; mt++)
        #pragma unroll
        for (int nt = 0; nt < 8; nt++)
            #pragma unroll
            for (int i = 0; i < 4; i++) acc[mt][nt][i] = 0.f;

    const int r8 = tid >> 3, seg = tid & 7;
    auto load = [&](int c, int s) {
        const int k0 = c*64;
        const uint32_t st = db + s*GSTG;
        #pragma unroll
        for (int i = 0; i < 4; i++) {
            const int rr = r8 + 32*i;
            const uint32_t sw = SWZ((uint32_t)(rr*128 + seg*16));
            const size_t ao = (size_t)(m0 + rr)*K + k0 + seg*8;
            const size_t bo = (size_t)(n0 + rr)*K + k0 + seg*8;
            cp16(st + sw,         Ah + ao);
            cp16(st + 16384 + sw, Al + ao);
            cp16(st + 32768 + sw, Bh + bo);
            cp16(st + 49152 + sw, Bl + bo);
        }
        CP_COMMIT();
    };

    const int nch = K / 64;
    load(0, 0);
    if (nch > 1) load(1, 1);

    for (int c = 0; c < nch; c++) {
        const int s = c & 1;
        if (c + 1 < nch) { CP_WAIT(1); } else { CP_WAIT(0); }
        __syncthreads();
        const uint32_t ab = db + s*GSTG, bb = ab + 32768;

        #pragma unroll
        for (int ks = 0; ks < 4; ks++) {
            const uint32_t cb = (uint32_t)(ks*32 + ((lane >> 4) & 1)*16);
            uint32_t a_h[2][4], a_l[2][4], b_h[8][2], b_l[8][2];
            #pragma unroll
            for (int mt = 0; mt < 2; mt++) {
                const uint32_t off = SWZ((uint32_t)((wm + mt*16 + (lane & 15))*128) + cb);
                ldsm4(a_h[mt][0], a_h[mt][1], a_h[mt][2], a_h[mt][3], ab + off);
                ldsm4(a_l[mt][0], a_l[mt][1], a_l[mt][2], a_l[mt][3], ab + 16384 + off);
            }
            #pragma unroll
            for (int np = 0; np < 4; np++) {
                const uint32_t off = SWZ((uint32_t)((wn + np*16 + (lane & 15))*128) + cb);
                uint32_t r0, r1, r2, r3;
                ldsm4(r0, r1, r2, r3, bb + off);
                b_h[np*2][0] = r0; b_h[np*2][1] = r2;
                b_h[np*2+1][0] = r1; b_h[np*2+1][1] = r3;
                ldsm4(r0, r1, r2, r3, bb + 16384 + off);
                b_l[np*2][0] = r0; b_l[np*2][1] = r2;
                b_l[np*2+1][0] = r1; b_l[np*2+1][1] = r3;
            }
            #pragma unroll
            for (int mt = 0; mt < 2; mt++)
                #pragma unroll
                for (int nt = 0; nt < 8; nt++) {
                    mma_bf16(acc[mt][nt], a_h[mt], b_h[nt]);
                    mma_bf16(acc[mt][nt], a_h[mt], b_l[nt]);
                    mma_bf16(acc[mt][nt], a_l[mt], b_h[nt]);
                }
        }
        __syncthreads();
        if (c + 2 < nch) load(c + 2, s);
    }

    // epilogue
    const int rr = lane >> 2, cc = (lane & 3)*2;
    #pragma unroll
    for (int mt = 0; mt < 2; mt++)
        #pragma unroll
        for (int nt = 0; nt < 8; nt++) {
            const int row = m0 + wm + mt*16 + rr;
            const int col = n0 + wn + nt*8 + cc;
            float b0 = bias ? bias[col] : 0.f, b1 = bias ? bias[col+1] : 0.f;
            float v00 = acc[mt][nt][0] + b0, v01 = acc[mt][nt][1] + b1;
            float v10 = acc[mt][nt][2] + b0, v11 = acc[mt][nt][3] + b1;
            if (Cf) {
                *reinterpret_cast<float2*>(&Cf[(size_t)row*ldc + col])     = make_float2(v00, v01);
                *reinterpret_cast<float2*>(&Cf[(size_t)(row+8)*ldc + col]) = make_float2(v10, v11);
            } else {
                uint32_t hi, lo;
                split_pack(v00, v01, hi, lo);
                *reinterpret_cast<uint32_t*>(&Ch[(size_t)row*ldc + col]) = hi;
                *reinterpret_cast<uint32_t*>(&Cl[(size_t)row*ldc + col]) = lo;
                split_pack(v10, v11, hi, lo);
                *reinterpret_cast<uint32_t*>(&Ch[(size_t)(row+8)*ldc + col]) = hi;
                *reinterpret_cast<uint32_t*>(&Cl[(size_t)(row+8)*ldc + col]) = lo;
            }
        }
}

// ---------------- hifi 2x2 window attention (fp32 in, split out) ----------------
__global__ __launch_bounds__(128) void hifi_attn_kernel(
    const float* __restrict__ qkv,
    __nv_bfloat16* __restrict__ oh, __nv_bfloat16* __restrict__ ol)
{
    const int warp = threadIdx.x >> 5, lane = threadIdx.x & 31;
    const int unit = blockIdx.x * 4 + warp;
    const int head = unit & 3, g = (unit >> 2) & 255, b = unit >> 10;
    const int gi = g >> 4, gj = g & 15;

    int n[4];
    #pragma unroll
    for (int t = 0; t < 4; t++)
        n[t] = (gi*2 + (t>>1)) * 32 + gj*2 + (t&1);

    float q[4][2], k[4][2], v[4][2];
    #pragma unroll
    for (int t = 0; t < 4; t++) {
        const float* p = qkv + (size_t)(b*SEQ + n[t]) * 768 + head*64;
        q[t][0]=p[lane];     q[t][1]=p[lane+32];
        k[t][0]=p[256+lane]; k[t][1]=p[256+lane+32];
        v[t][0]=p[512+lane]; v[t][1]=p[512+lane+32];
    }
    float s[4][4];
    #pragma unroll
    for (int t = 0; t < 4; t++)
        #pragma unroll
        for (int u = 0; u < 4; u++)
            s[t][u] = q[t][0]*k[u][0] + q[t][1]*k[u][1];
    #pragma unroll
    for (int off = 16; off >= 1; off >>= 1)
        #pragma unroll
        for (int t = 0; t < 4; t++)
            #pragma unroll
            for (int u = 0; u < 4; u++)
                s[t][u] += __shfl_xor_sync(0xffffffffu, s[t][u], off);
    #pragma unroll
    for (int t = 0; t < 4; t++) {
        float s0=s[t][0]*SCALE, s1=s[t][1]*SCALE, s2=s[t][2]*SCALE, s3=s[t][3]*SCALE;
        float mx = fmaxf(fmaxf(s0,s1), fmaxf(s2,s3));
        float e0=__expf(s0-mx), e1=__expf(s1-mx), e2=__expf(s2-mx), e3=__expf(s3-mx);
        float inv = 1.f/(e0+e1+e2+e3);
        e0*=inv; e1*=inv; e2*=inv; e3*=inv;
        float o0 = e0*v[0][0]+e1*v[1][0]+e2*v[2][0]+e3*v[3][0];
        float o1 = e0*v[0][1]+e1*v[1][1]+e2*v[2][1]+e3*v[3][1];
        size_t base = (size_t)(b*SEQ + n[t]) * 256 + head*64;
        __nv_bfloat16 h, l;
        split2(o0,h,l); oh[base+lane]=h;    ol[base+lane]=l;
        split2(o1,h,l); oh[base+lane+32]=h; ol[base+lane+32]=l;
    }
}

// ---------------- HMMA flash attention ----------------
// 64 q-rows per CTA (4 warps x m16), head_dim 64, split bf16 in/out.
// smem: Qh/Ql (16KB) + 2 stages of Kh/Kl/Vh/Vl (32KB each).
#define FSTG 32768
#define FLASH_SMEM (1024 + 16384 + 2*FSTG)

__global__ __launch_bounds__(128, 1) void flash_mma_kernel(
    const __nv_bfloat16* __restrict__ Qh, const __nv_bfloat16* __restrict__ Ql,
    const __nv_bfloat16* __restrict__ Kh, const __nv_bfloat16* __restrict__ Kl,
    const __nv_bfloat16* __restrict__ Vh, const __nv_bfloat16* __restrict__ Vl,
    __nv_bfloat16* __restrict__ Oh, __nv_bfloat16* __restrict__ Ol,
    int qrs, int krs, int ors, int seq)
{
    extern __shared__ char smem[];
    const uint32_t sb = s2u(smem);
    const uint32_t db = (sb + 1023u) & ~1023u;
    const int tid = threadIdx.x, wid = tid >> 5, lane = tid & 31;
    const int b = blockIdx.z, head = blockIdx.y, qt = blockIdx.x;
    const size_t bo = (size_t)b * seq;

    const __nv_bfloat16* qhp = Qh + (bo + qt*64)*qrs + head*64;
    const __nv_bfloat16* qlp = Ql + (bo + qt*64)*qrs + head*64;
    const __nv_bfloat16* khp = Kh + bo*krs + head*64;
    const __nv_bfloat16* klp = Kl + bo*krs + head*64;
    const __nv_bfloat16* vhp = Vh + bo*krs + head*64;
    const __nv_bfloat16* vlp = Vl + bo*krs + head*64;

    const int r8 = tid >> 3, seg = tid & 7;

    // Q load (both halves)
    #pragma unroll
    for (int i = 0; i < 4; i++) {
        const int rr = r8 + 16*i;
        const uint32_t sw = SWZ((uint32_t)(rr*128 + seg*16));
        cp16(db + sw,        qhp + (size_t)rr*qrs + seg*8);
        cp16(db + 8192 + sw, qlp + (size_t)rr*qrs + seg*8);
    }
    CP_COMMIT();

    const uint32_t kvb = db + 16384;
    auto load_kv = [&](int kt, int s) {
        const uint32_t st = kvb + s*FSTG;
        const size_t rb = (size_t)kt * 64;
        #pragma unroll
        for (int i = 0; i < 4; i++) {
            const int rr = r8 + 16*i;
            const uint32_t sw = SWZ((uint32_t)(rr*128 + seg*16));
            const size_t o = (rb + rr)*krs + seg*8;
            cp16(st + sw,         khp + o);
            cp16(st + 8192 + sw,  klp + o);
            cp16(st + 16384 + sw, vhp + o);
            cp16(st + 24576 + sw, vlp + o);
        }
        CP_COMMIT();
    };
    const int ntiles = seq >> 6;
    load_kv(0, 0);
    if (ntiles > 1) load_kv(1, 1);

    CP_WAIT(1);        // Q + KV0 complete
    __syncthreads();

    // Q fragments (register resident)
    uint32_t qfh[4][4], qfl[4][4];
    {
        const int arow = wid*16 + (lane & 15);
        #pragma unroll
        for (int ks = 0; ks < 4; ks++) {
            const uint32_t off = SWZ((uint32_t)(arow*128 + ks*32 + ((lane >> 4) & 1)*16));
            ldsm4(qfh[ks][0], qfh[ks][1], qfh[ks][2], qfh[ks][3], db + off);
            ldsm4(qfl[ks][0], qfl[ks][1], qfl[ks][2], qfl[ks][3], db + 8192 + off);
        }
    }

    float m0 = -1e30f, m1 = -1e30f, l0 = 0.f, l1 = 0.f;
    float oacc[8][4];
    #pragma unroll
    for (int nt = 0; nt < 8; nt++)
        #pragma unroll
        for (int i = 0; i < 4; i++) oacc[nt][i] = 0.f;

    for (int kt = 0; kt < ntiles; kt++) {
        if (kt > 0) {
            if (kt + 1 < ntiles) { CP_WAIT(1); } else { CP_WAIT(0); }
            __syncthreads();
        }
        const uint32_t st = kvb + (kt & 1)*FSTG;

        // S = Q K^T
        float sacc[8][4];
        #pragma unroll
        for (int nt = 0; nt < 8; nt++)
            #pragma unroll
            for (int i = 0; i < 4; i++) sacc[nt][i] = 0.f;

        #pragma unroll
        for (int ks = 0; ks < 4; ks++) {
            const uint32_t cb = (uint32_t)(ks*32 + ((lane >> 4) & 1)*16);
            uint32_t b_h[8][2], b_l[8][2];
            #pragma unroll
            for (int np = 0; np < 4; np++) {
                const uint32_t off = SWZ((uint32_t)((np*16 + (lane & 15))*128) + cb);
                uint32_t r0, r1, r2, r3;
                ldsm4(r0, r1, r2, r3, st + off);
                b_h[np*2][0] = r0; b_h[np*2][1] = r2;
                b_h[np*2+1][0] = r1; b_h[np*2+1][1] = r3;
                ldsm4(r0, r1, r2, r3, st + 8192 + off);
                b_l[np*2][0] = r0; b_l[np*2][1] = r2;
                b_l[np*2+1][0] = r1; b_l[np*2+1][1] = r3;
            }
            #pragma unroll
            for (int nt = 0; nt < 8; nt++) {
                mma_bf16(sacc[nt], qfh[ks], b_h[nt]);
                mma_bf16(sacc[nt], qfh[ks], b_l[nt]);
                mma_bf16(sacc[nt], qfl[ks], b_h[nt]);
            }
        }

        // online softmax (rows r = lane>>2 and r+8; quad lanes share a row)
        float rx0 = -1e30f, rx1 = -1e30f;
        #pragma unroll
        for (int nt = 0; nt < 8; nt++) {
            #pragma unroll
            for (int i = 0; i < 4; i++) sacc[nt][i] *= SCALE;
            rx0 = fmaxf(rx0, fmaxf(sacc[nt][0], sacc[nt][1]));
            rx1 = fmaxf(rx1, fmaxf(sacc[nt][2], sacc[nt][3]));
        }
        #pragma unroll
        for (int off = 1; off <= 2; off <<= 1) {
            rx0 = fmaxf(rx0, __shfl_xor_sync(0xffffffffu, rx0, off));
            rx1 = fmaxf(rx1, __shfl_xor_sync(0xffffffffu, rx1, off));
        }
        const float mn0 = fmaxf(m0, rx0), mn1 = fmaxf(m1, rx1);
        const float cr0 = __expf(m0 - mn0), cr1 = __expf(m1 - mn1);
        float rs0 = 0.f, rs1 = 0.f;
        #pragma unroll
        for (int nt = 0; nt < 8; nt++) {
            sacc[nt][0] = __expf(sacc[nt][0] - mn0);
            sacc[nt][1] = __expf(sacc[nt][1] - mn0);
            sacc[nt][2] = __expf(sacc[nt][2] - mn1);
            sacc[nt][3] = __expf(sacc[nt][3] - mn1);
            rs0 += sacc[nt][0] + sacc[nt][1];
            rs1 += sacc[nt][2] + sacc[nt][3];
        }
        #pragma unroll
        for (int off = 1; off <= 2; off <<= 1) {
            rs0 += __shfl_xor_sync(0xffffffffu, rs0, off);
            rs1 += __shfl_xor_sync(0xffffffffu, rs1, off);
        }
        l0 = l0*cr0 + rs0; l1 = l1*cr1 + rs1;
        m0 = mn0; m1 = mn1;
        #pragma unroll
        for (int nt = 0; nt < 8; nt++) {
            oacc[nt][0] *= cr0; oacc[nt][1] *= cr0;
            oacc[nt][2] *= cr1; oacc[nt][3] *= cr1;
        }

        // O += P V  (P a-frags packed straight from sacc)
        #pragma unroll
        for (int j = 0; j < 4; j++) {
            uint32_t pa_h[4], pa_l[4];
            split_pack(sacc[2*j][0],   sacc[2*j][1],   pa_h[0], pa_l[0]);
            split_pack(sacc[2*j][2],   sacc[2*j][3],   pa_h[1], pa_l[1]);
            split_pack(sacc[2*j+1][0], sacc[2*j+1][1], pa_h[2], pa_l[2]);
            split_pack(sacc[2*j+1][2], sacc[2*j+1][3], pa_h[3], pa_l[3]);

            uint32_t v_h[8][2], v_l[8][2];
            const int srow = j*16 + (lane & 15);
            #pragma unroll
            for (int np = 0; np < 4; np++) {
                const uint32_t off = SWZ((uint32_t)(srow*128 + np*32 + ((lane >> 4) & 1)*16));
                uint32_t r0, r1, r2, r3;
                ldsm4t(r0, r1, r2, r3, st + 16384 + off);
                v_h[np*2][0] = r0; v_h[np*2][1] = r1;
                v_h[np*2+1][0] = r2; v_h[np*2+1][1] = r3;
                ldsm4t(r0, r1, r2, r3, st + 24576 + off);
                v_l[np*2][0] = r0; v_l[np*2][1] = r1;
                v_l[np*2+1][0] = r2; v_l[np*2+1][1] = r3;
            }
            #pragma unroll
            for (int nt = 0; nt < 8; nt++) {
                mma_bf16(oacc[nt], pa_h, v_h[nt]);
                mma_bf16(oacc[nt], pa_h, v_l[nt]);
                mma_bf16(oacc[nt], pa_l, v_h[nt]);
            }
        }
        __syncthreads();
        if (kt + 2 < ntiles) load_kv(kt + 2, kt & 1);
    }

    // output (split bf16)
    const float inv0 = 1.f / l0, inv1 = 1.f / l1;
    const int rr = lane >> 2, cc = (lane & 3)*2;
    const size_t row0 = bo + qt*64 + wid*16 + rr;
    #pragma unroll
    for (int nt = 0; nt < 8; nt++) {
        const int col = head*64 + nt*8 + cc;
        uint32_t hi, lo;
        split_pack(oacc[nt][0]*inv0, oacc[nt][1]*inv0, hi, lo);
        *reinterpret_cast<uint32_t*>(&Oh[row0*ors + col]) = hi;
        *reinterpret_cast<uint32_t*>(&Ol[row0*ors + col]) = lo;
        split_pack(oacc[nt][2]*inv1, oacc[nt][3]*inv1, hi, lo);
        *reinterpret_cast<uint32_t*>(&Oh[(row0+8)*ors + col]) = hi;
        *reinterpret_cast<uint32_t*>(&Ol[(row0+8)*ors + col]) = lo;
    }
}

// ---------------- launch ----------------
extern "C" void kernel_launch(void* const* d_in, const int* in_sizes, int n_in,
                              void* d_out, int out_size)
{
    const float* x         = (const float*)d_in[0];
    const float* pos_emb   = (const float*)d_in[1];
    const float* l_q_w     = (const float*)d_in[2];
    const float* l_kv_w    = (const float*)d_in[3];
    const float* l_proj_w  = (const float*)d_in[4];
    const float* l_proj_b  = (const float*)d_in[5];
    const float* h_qkv_w   = (const float*)d_in[6];
    const float* h_proj_w  = (const float*)d_in[7];
    const float* h_proj_b  = (const float*)d_in[8];
    const float* in_proj_w = (const float*)d_in[9];
    const float* in_proj_b = (const float*)d_in[10];
    const float* out_proj_w= (const float*)d_in[11];
    const float* out_proj_b= (const float*)d_in[12];
    float* out = (float*)d_out;

    float* qkvh;
    __nv_bfloat16 *xph,*xpl,*qlh,*qll,*kvh,*kvl,*qmh,*qml;
    __nv_bfloat16 *hh,*hl,*lh,*ll,*yh,*yl,*mh,*ml;
    __nv_bfloat16 *w0h,*w0l,*w1h,*w1l,*w2h,*w2l,*w3h,*w3l,*w4h,*w4l,*w5h,*w5l,*w6h,*w6l;
    cudaGetSymbolAddress((void**)&qkvh, g_qkv_h);
    cudaGetSymbolAddress((void**)&xph, g_xp_h);   cudaGetSymbolAddress((void**)&xpl, g_xp_l);
    cudaGetSymbolAddress((void**)&qlh, g_ql_h);   cudaGetSymbolAddress((void**)&qll, g_ql_l);
    cudaGetSymbolAddress((void**)&kvh, g_kvl_h);  cudaGetSymbolAddress((void**)&kvl, g_kvl_l);
    cudaGetSymbolAddress((void**)&qmh, g_qm_h);   cudaGetSymbolAddress((void**)&qml, g_qm_l);
    cudaGetSymbolAddress((void**)&hh,  g_hifi_h); cudaGetSymbolAddress((void**)&hl,  g_hifi_l);
    cudaGetSymbolAddress((void**)&lh,  g_lofi_h); cudaGetSymbolAddress((void**)&ll,  g_lofi_l);
    cudaGetSymbolAddress((void**)&yh,  g_y_h);    cudaGetSymbolAddress((void**)&yl,  g_y_l);
    cudaGetSymbolAddress((void**)&mh,  g_mha_h);  cudaGetSymbolAddress((void**)&ml,  g_mha_l);
    cudaGetSymbolAddress((void**)&w0h, g_w0h); cudaGetSymbolAddress((void**)&w0l, g_w0l);
    cudaGetSymbolAddress((void**)&w1h, g_w1h); cudaGetSymbolAddress((void**)&w1l, g_w1l);
    cudaGetSymbolAddress((void**)&w2h, g_w2h); cudaGetSymbolAddress((void**)&w2l, g_w2l);
    cudaGetSymbolAddress((void**)&w3h, g_w3h); cudaGetSymbolAddress((void**)&w3l, g_w3l);
    cudaGetSymbolAddress((void**)&w4h, g_w4h); cudaGetSymbolAddress((void**)&w4l, g_w4l);
    cudaGetSymbolAddress((void**)&w5h, g_w5h); cudaGetSymbolAddress((void**)&w5l, g_w5l);
    cudaGetSymbolAddress((void**)&w6h, g_w6h); cudaGetSymbolAddress((void**)&w6l, g_w6l);

    cudaFuncSetAttribute(gemm_mma_kernel,  cudaFuncAttributeMaxDynamicSharedMemorySize, GEMM_SMEM);
    cudaFuncSetAttribute(flash_mma_kernel, cudaFuncAttributeMaxDynamicSharedMemorySize, FLASH_SMEM);

    const int M = MTOT;
    const dim3 wb(32, 8);

    add_pos_split_kernel<<<(M*CDIM/4 + 255)/256, 256>>>(x, pos_emb, xph, xpl);

    wsplit_kernel<<<dim3(768/32, 512/32),  wb>>>(h_qkv_w,   w0h, w0l, 512, 768);
    wsplit_kernel<<<dim3(256/32, 512/32),  wb>>>(l_q_w,     w1h, w1l, 512, 256);
    wsplit_kernel<<<dim3(512/32, 512/32),  wb>>>(l_kv_w,    w2h, w2l, 512, 512);
    wsplit_kernel<<<dim3(256/32, 256/32),  wb>>>(h_proj_w,  w3h, w3l, 256, 256);
    wsplit_kernel<<<dim3(256/32, 256/32),  wb>>>(l_proj_w,  w4h, w4l, 256, 256);
    wsplit_kernel<<<dim3(1536/32, 512/32), wb>>>(in_proj_w, w5h, w5l, 512, 1536);
    wsplit_kernel<<<dim3(512/32, 512/32),  wb>>>(out_proj_w,w6h, w6l, 512, 512);

    // projections
    gemm_mma_kernel<<<dim3(6, M/128), 256, GEMM_SMEM>>>(xph, xpl, w0h, w0l, nullptr, qkvh, nullptr, nullptr, 768, 512, 768);
    gemm_mma_kernel<<<dim3(2, M/128), 256, GEMM_SMEM>>>(xph, xpl, w1h, w1l, nullptr, nullptr, qlh, qll, 256, 512, 256);
    gemm_mma_kernel<<<dim3(4, M/128), 256, GEMM_SMEM>>>(xph, xpl, w2h, w2l, nullptr, nullptr, kvh, kvl, 512, 512, 512);

    // attention branches
    hifi_attn_kernel<<<4096, 128>>>(qkvh, hh, hl);
    flash_mma_kernel<<<dim3(SEQ/64, 4, BATCH), 128, FLASH_SMEM>>>(
        qlh, qll, kvh, kvl, kvh + 256, kvl + 256, lh, ll, 256, 512, 256, SEQ);

    // branch projections -> split y
    gemm_mma_kernel<<<dim3(2, M/128), 256, GEMM_SMEM>>>(hh, hl, w3h, w3l, h_proj_b, nullptr, yh,       yl,       256, 256, 512);
    gemm_mma_kernel<<<dim3(2, M/128), 256, GEMM_SMEM>>>(lh, ll, w4h, w4l, l_proj_b, nullptr, yh + 256, yl + 256, 256, 256, 512);

    // final MHA
    gemm_mma_kernel<<<dim3(12, M/128), 256, GEMM_SMEM>>>(yh, yl, w5h, w5l, in_proj_b, nullptr, qmh, qml, 1536, 512, 1536);
    flash_mma_kernel<<<dim3(SEQ/64, 8, BATCH), 128, FLASH_SMEM>>>(
        qmh, qml, qmh + 512, qml + 512, qmh + 1024, qml + 1024, mh, ml, 1536, 1536, 512, SEQ);
    gemm_mma_kernel<<<dim3(4, M/128), 256, GEMM_SMEM>>>(mh, ml, w6h, w6l, out_proj_b, out, nullptr, nullptr, 512, 512, 512);
}

// round 5
// speedup vs baseline: 5.2560x; 1.0894x over previous
#include <cuda_runtime.h>
#include <cuda_bf16.h>
#include <math.h>
#include <stdint.h>

#define BATCH 16
#define SEQ   1024
#define CDIM  512
#define SCALE 0.125f
#define MTOT  (BATCH*SEQ)

// ---------------- scratch ----------------
__device__ __nv_bfloat16 g_cat_h[MTOT*1536], g_cat_l[MTOT*1536];  // [hifi qkv | l_q | l_k | l_v]
__device__ __nv_bfloat16 g_qm_h [MTOT*1536], g_qm_l [MTOT*1536];
__device__ __nv_bfloat16 g_xp_h [MTOT*CDIM], g_xp_l [MTOT*CDIM];
__device__ __nv_bfloat16 g_hifi_h[MTOT*256], g_hifi_l[MTOT*256];
__device__ __nv_bfloat16 g_lofi_h[MTOT*256], g_lofi_l[MTOT*256];
__device__ __nv_bfloat16 g_y_h  [MTOT*512],  g_y_l  [MTOT*512];
__device__ __nv_bfloat16 g_mha_h[MTOT*512],  g_mha_l[MTOT*512];
__device__ __nv_bfloat16 g_wch[1536*512], g_wcl[1536*512];        // cat weights^T
__device__ __nv_bfloat16 g_w3h[256*256],  g_w3l[256*256];
__device__ __nv_bfloat16 g_w4h[256*256],  g_w4l[256*256];
__device__ __nv_bfloat16 g_w5h[1536*512], g_w5l[1536*512];
__device__ __nv_bfloat16 g_w6h[512*512],  g_w6l[512*512];

// ---------------- helpers ----------------
__device__ __forceinline__ uint32_t s2u(const void* p) {
    return (uint32_t)__cvta_generic_to_shared(p);
}
#define SWZ(o) ((o) ^ (((o) >> 3) & 0x70))

__device__ __forceinline__ void cp16(uint32_t smem, const void* g) {
    asm volatile("cp.async.cg.shared.global [%0], [%1], 16;"
                 :: "r"(smem), "l"(__cvta_generic_to_global(g)));
}
#define CP_COMMIT() asm volatile("cp.async.commit_group;" ::: "memory")
#define CP_WAIT(n)  asm volatile("cp.async.wait_group %0;" :: "n"(n) : "memory")

__device__ __forceinline__ void ldsm4(uint32_t& r0, uint32_t& r1, uint32_t& r2, uint32_t& r3,
                                      uint32_t a) {
    asm volatile("ldmatrix.sync.aligned.m8n8.x4.shared.b16 {%0,%1,%2,%3}, [%4];"
                 : "=r"(r0), "=r"(r1), "=r"(r2), "=r"(r3) : "r"(a));
}
__device__ __forceinline__ void ldsm4t(uint32_t& r0, uint32_t& r1, uint32_t& r2, uint32_t& r3,
                                       uint32_t a) {
    asm volatile("ldmatrix.sync.aligned.m8n8.x4.trans.shared.b16 {%0,%1,%2,%3}, [%4];"
                 : "=r"(r0), "=r"(r1), "=r"(r2), "=r"(r3) : "r"(a));
}
__device__ __forceinline__ void mma_bf16(float* d, const uint32_t* a, const uint32_t* b) {
    asm volatile("mma.sync.aligned.m16n8k16.row.col.f32.bf16.bf16.f32 "
                 "{%0,%1,%2,%3}, {%4,%5,%6,%7}, {%8,%9}, {%0,%1,%2,%3};"
                 : "+f"(d[0]), "+f"(d[1]), "+f"(d[2]), "+f"(d[3])
                 : "r"(a[0]), "r"(a[1]), "r"(a[2]), "r"(a[3]), "r"(b[0]), "r"(b[1]));
}

__device__ __forceinline__ void split2(float x, __nv_bfloat16& h, __nv_bfloat16& l) {
    h = __float2bfloat16_rn(x);
    l = __float2bfloat16_rn(x - __bfloat162float(h));
}
__device__ __forceinline__ void split_pack(float x, float y, uint32_t& hi, uint32_t& lo) {
    __nv_bfloat162 h2, l2;
    split2(x, h2.x, l2.x);
    split2(y, h2.y, l2.y);
    hi = *reinterpret_cast<uint32_t*>(&h2);
    lo = *reinterpret_cast<uint32_t*>(&l2);
}

// ---------------- x + pos -> hi/lo split ----------------
__global__ __launch_bounds__(256) void add_pos_split_kernel(
    const float* __restrict__ x, const float* __restrict__ pos,
    __nv_bfloat16* __restrict__ oh, __nv_bfloat16* __restrict__ ol)
{
    const int per_b4 = SEQ*CDIM/4;
    int i = blockIdx.x * blockDim.x + threadIdx.x;
    float4 a = reinterpret_cast<const float4*>(x)[i];
    float4 p = reinterpret_cast<const float4*>(pos)[i % per_b4];
    __nv_bfloat162 h01, h23, l01, l23;
    split2(a.x+p.x, h01.x, l01.x); split2(a.y+p.y, h01.y, l01.y);
    split2(a.z+p.z, h23.x, l23.x); split2(a.w+p.w, h23.y, l23.y);
    *reinterpret_cast<__nv_bfloat162*>(&oh[i*4])   = h01;
    *reinterpret_cast<__nv_bfloat162*>(&oh[i*4+2]) = h23;
    *reinterpret_cast<__nv_bfloat162*>(&ol[i*4])   = l01;
    *reinterpret_cast<__nv_bfloat162*>(&ol[i*4+2]) = l23;
}

// ---------------- weight transpose + split: W[K][N] -> T[N][K] ----------------
__global__ __launch_bounds__(256) void wsplit_kernel(
    const float* __restrict__ W, __nv_bfloat16* __restrict__ Th,
    __nv_bfloat16* __restrict__ Tl, int K, int N)
{
    __shared__ float ts[32][33];
    const int n0 = blockIdx.x*32, k0 = blockIdx.y*32;
    const int x = threadIdx.x, y = threadIdx.y;
    #pragma unroll
    for (int r = 0; r < 4; r++)
        ts[y + r*8][x] = W[(size_t)(k0 + y + r*8)*N + n0 + x];
    __syncthreads();
    #pragma unroll
    for (int r = 0; r < 4; r++) {
        __nv_bfloat16 h, l;
        split2(ts[x][y + r*8], h, l);
        size_t o = (size_t)(n0 + y + r*8)*K + k0 + x;
        Th[o] = h; Tl[o] = l;
    }
}

// ---------------- HMMA split-bf16 GEMM ----------------
// C[M,N] = (Ah+Al)[M,K] @ (Bh+Bl)[N,K]^T + bias; out fp32 (Cf) or split (Ch/Cl)
// BM=128, BN=64, BK=64, 256 threads (8 warps: 4 M x 2 N), 2-stage cp.async.
// smem/stage: Ah 16K | Al 16K | Bh 8K | Bl 8K = 48K; total 97KB -> 2 CTAs/SM.
#define GSTG 49152
#define GEMM_SMEM (1024 + 2*GSTG)

__global__ __launch_bounds__(256, 2) void gemm_mma_kernel(
    const __nv_bfloat16* __restrict__ Ah, const __nv_bfloat16* __restrict__ Al,
    const __nv_bfloat16* __restrict__ Bh, const __nv_bfloat16* __restrict__ Bl,
    const float* __restrict__ bias, float* __restrict__ Cf,
    __nv_bfloat16* __restrict__ Ch, __nv_bfloat16* __restrict__ Cl,
    int N, int K, int ldc)
{
    extern __shared__ char smem[];
    const uint32_t sb = s2u(smem);
    const uint32_t db = (sb + 1023u) & ~1023u;
    const int tid = threadIdx.x, wid = tid >> 5, lane = tid & 31;
    const int m0 = blockIdx.y*128, n0 = blockIdx.x*64;
    const int wm = (wid & 3)*32, wn = (wid >> 2)*32;

    float acc[2][4][4];
    #pragma unroll
    for (int mt = 0; mt < 2; mt++)
        #pragma unroll
        for (int nt = 0; nt < 4; nt++)
            #pragma unroll
            for (int i = 0; i < 4; i++) acc[mt][nt][i] = 0.f;

    const int r8 = tid >> 3, seg = tid & 7;
    auto load = [&](int c, int s) {
        const int k0 = c*64;
        const uint32_t st = db + s*GSTG;
        #pragma unroll
        for (int i = 0; i < 4; i++) {
            const int rr = r8 + 32*i;
            const uint32_t sw = SWZ((uint32_t)(rr*128 + seg*16));
            const size_t ao = (size_t)(m0 + rr)*K + k0 + seg*8;
            cp16(st + sw,         Ah + ao);
            cp16(st + 16384 + sw, Al + ao);
        }
        #pragma unroll
        for (int i = 0; i < 2; i++) {
            const int rr = r8 + 32*i;
            const uint32_t sw = SWZ((uint32_t)(rr*128 + seg*16));
            const size_t bo = (size_t)(n0 + rr)*K + k0 + seg*8;
            cp16(st + 32768 + sw, Bh + bo);
            cp16(st + 40960 + sw, Bl + bo);
        }
        CP_COMMIT();
    };

    const int nch = K / 64;
    load(0, 0);
    if (nch > 1) load(1, 1);

    for (int c = 0; c < nch; c++) {
        const int s = c & 1;
        if (c + 1 < nch) { CP_WAIT(1); } else { CP_WAIT(0); }
        __syncthreads();
        const uint32_t ab = db + s*GSTG, bb = ab + 32768;

        #pragma unroll
        for (int ks = 0; ks < 4; ks++) {
            const uint32_t cb = (uint32_t)(ks*32 + ((lane >> 4) & 1)*16);
            uint32_t a_h[2][4], a_l[2][4], b_h[4][2], b_l[4][2];
            #pragma unroll
            for (int mt = 0; mt < 2; mt++) {
                const uint32_t off = SWZ((uint32_t)((wm + mt*16 + (lane & 15))*128) + cb);
                ldsm4(a_h[mt][0], a_h[mt][1], a_h[mt][2], a_h[mt][3], ab + off);
                ldsm4(a_l[mt][0], a_l[mt][1], a_l[mt][2], a_l[mt][3], ab + 16384 + off);
            }
            #pragma unroll
            for (int np = 0; np < 2; np++) {
                const uint32_t off = SWZ((uint32_t)((wn + np*16 + (lane & 15))*128) + cb);
                uint32_t r0, r1, r2, r3;
                ldsm4(r0, r1, r2, r3, bb + off);
                b_h[np*2][0] = r0; b_h[np*2][1] = r2;
                b_h[np*2+1][0] = r1; b_h[np*2+1][1] = r3;
                ldsm4(r0, r1, r2, r3, bb + 8192 + off);
                b_l[np*2][0] = r0; b_l[np*2][1] = r2;
                b_l[np*2+1][0] = r1; b_l[np*2+1][1] = r3;
            }
            #pragma unroll
            for (int mt = 0; mt < 2; mt++)
                #pragma unroll
                for (int nt = 0; nt < 4; nt++) {
                    mma_bf16(acc[mt][nt], a_h[mt], b_h[nt]);
                    mma_bf16(acc[mt][nt], a_h[mt], b_l[nt]);
                    mma_bf16(acc[mt][nt], a_l[mt], b_h[nt]);
                }
        }
        __syncthreads();
        if (c + 2 < nch) load(c + 2, s);
    }

    // epilogue
    const int rr = lane >> 2, cc = (lane & 3)*2;
    #pragma unroll
    for (int mt = 0; mt < 2; mt++)
        #pragma unroll
        for (int nt = 0; nt < 4; nt++) {
            const int row = m0 + wm + mt*16 + rr;
            const int col = n0 + wn + nt*8 + cc;
            float b0 = bias ? bias[col] : 0.f, b1 = bias ? bias[col+1] : 0.f;
            float v00 = acc[mt][nt][0] + b0, v01 = acc[mt][nt][1] + b1;
            float v10 = acc[mt][nt][2] + b0, v11 = acc[mt][nt][3] + b1;
            if (Cf) {
                *reinterpret_cast<float2*>(&Cf[(size_t)row*ldc + col])     = make_float2(v00, v01);
                *reinterpret_cast<float2*>(&Cf[(size_t)(row+8)*ldc + col]) = make_float2(v10, v11);
            } else {
                uint32_t hi, lo;
                split_pack(v00, v01, hi, lo);
                *reinterpret_cast<uint32_t*>(&Ch[(size_t)row*ldc + col]) = hi;
                *reinterpret_cast<uint32_t*>(&Cl[(size_t)row*ldc + col]) = lo;
                split_pack(v10, v11, hi, lo);
                *reinterpret_cast<uint32_t*>(&Ch[(size_t)(row+8)*ldc + col]) = hi;
                *reinterpret_cast<uint32_t*>(&Cl[(size_t)(row+8)*ldc + col]) = lo;
            }
        }
}

// ---------------- hifi 2x2 window attention (split bf16 in/out) ----------------
// cat layout per row (stride 1536): q 0-255, k 256-511, v 512-767
__global__ __launch_bounds__(128) void hifi_attn_kernel(
    const __nv_bfloat16* __restrict__ ch, const __nv_bfloat16* __restrict__ cl,
    __nv_bfloat16* __restrict__ oh, __nv_bfloat16* __restrict__ ol)
{
    const int warp = threadIdx.x >> 5, lane = threadIdx.x & 31;
    const int unit = blockIdx.x * 4 + warp;
    const int head = unit & 3, g = (unit >> 2) & 255, b = unit >> 10;
    const int gi = g >> 4, gj = g & 15;

    int n[4];
    #pragma unroll
    for (int t = 0; t < 4; t++)
        n[t] = (gi*2 + (t>>1)) * 32 + gj*2 + (t&1);

    float q[4][2], k[4][2], v[4][2];
    #pragma unroll
    for (int t = 0; t < 4; t++) {
        const size_t p = (size_t)(b*SEQ + n[t]) * 1536 + head*64;
        q[t][0] = __bfloat162float(ch[p+lane])        + __bfloat162float(cl[p+lane]);
        q[t][1] = __bfloat162float(ch[p+lane+32])     + __bfloat162float(cl[p+lane+32]);
        k[t][0] = __bfloat162float(ch[p+256+lane])    + __bfloat162float(cl[p+256+lane]);
        k[t][1] = __bfloat162float(ch[p+256+lane+32]) + __bfloat162float(cl[p+256+lane+32]);
        v[t][0] = __bfloat162float(ch[p+512+lane])    + __bfloat162float(cl[p+512+lane]);
        v[t][1] = __bfloat162float(ch[p+512+lane+32]) + __bfloat162float(cl[p+512+lane+32]);
    }
    float s[4][4];
    #pragma unroll
    for (int t = 0; t < 4; t++)
        #pragma unroll
        for (int u = 0; u < 4; u++)
            s[t][u] = q[t][0]*k[u][0] + q[t][1]*k[u][1];
    #pragma unroll
    for (int off = 16; off >= 1; off >>= 1)
        #pragma unroll
        for (int t = 0; t < 4; t++)
            #pragma unroll
            for (int u = 0; u < 4; u++)
                s[t][u] += __shfl_xor_sync(0xffffffffu, s[t][u], off);
    #pragma unroll
    for (int t = 0; t < 4; t++) {
        float s0=s[t][0]*SCALE, s1=s[t][1]*SCALE, s2=s[t][2]*SCALE, s3=s[t][3]*SCALE;
        float mx = fmaxf(fmaxf(s0,s1), fmaxf(s2,s3));
        float e0=__expf(s0-mx), e1=__expf(s1-mx), e2=__expf(s2-mx), e3=__expf(s3-mx);
        float inv = 1.f/(e0+e1+e2+e3);
        e0*=inv; e1*=inv; e2*=inv; e3*=inv;
        float o0 = e0*v[0][0]+e1*v[1][0]+e2*v[2][0]+e3*v[3][0];
        float o1 = e0*v[0][1]+e1*v[1][1]+e2*v[2][1]+e3*v[3][1];
        size_t base = (size_t)(b*SEQ + n[t]) * 256 + head*64;
        __nv_bfloat16 h, l;
        split2(o0,h,l); oh[base+lane]=h;    ol[base+lane]=l;
        split2(o1,h,l); oh[base+lane+32]=h; ol[base+lane+32]=l;
    }
}

// ---------------- HMMA flash attention ----------------
#define FSTG 32768
#define FLASH_SMEM (1024 + 16384 + 2*FSTG)

__global__ __launch_bounds__(128, 1) void flash_mma_kernel(
    const __nv_bfloat16* __restrict__ Qh, const __nv_bfloat16* __restrict__ Ql,
    const __nv_bfloat16* __restrict__ Kh, const __nv_bfloat16* __restrict__ Kl,
    const __nv_bfloat16* __restrict__ Vh, const __nv_bfloat16* __restrict__ Vl,
    __nv_bfloat16* __restrict__ Oh, __nv_bfloat16* __restrict__ Ol,
    int qrs, int krs, int ors, int seq)
{
    extern __shared__ char smem[];
    const uint32_t sb = s2u(smem);
    const uint32_t db = (sb + 1023u) & ~1023u;
    const int tid = threadIdx.x, wid = tid >> 5, lane = tid & 31;
    const int b = blockIdx.z, head = blockIdx.y, qt = blockIdx.x;
    const size_t bo = (size_t)b * seq;

    const __nv_bfloat16* qhp = Qh + (bo + qt*64)*qrs + head*64;
    const __nv_bfloat16* qlp = Ql + (bo + qt*64)*qrs + head*64;
    const __nv_bfloat16* khp = Kh + bo*krs + head*64;
    const __nv_bfloat16* klp = Kl + bo*krs + head*64;
    const __nv_bfloat16* vhp = Vh + bo*krs + head*64;
    const __nv_bfloat16* vlp = Vl + bo*krs + head*64;

    const int r8 = tid >> 3, seg = tid & 7;

    #pragma unroll
    for (int i = 0; i < 4; i++) {
        const int rr = r8 + 16*i;
        const uint32_t sw = SWZ((uint32_t)(rr*128 + seg*16));
        cp16(db + sw,        qhp + (size_t)rr*qrs + seg*8);
        cp16(db + 8192 + sw, qlp + (size_t)rr*qrs + seg*8);
    }
    CP_COMMIT();

    const uint32_t kvb = db + 16384;
    auto load_kv = [&](int kt, int s) {
        const uint32_t st = kvb + s*FSTG;
        const size_t rb = (size_t)kt * 64;
        #pragma unroll
        for (int i = 0; i < 4; i++) {
            const int rr = r8 + 16*i;
            const uint32_t sw = SWZ((uint32_t)(rr*128 + seg*16));
            const size_t o = (rb + rr)*krs + seg*8;
            cp16(st + sw,         khp + o);
            cp16(st + 8192 + sw,  klp + o);
            cp16(st + 16384 + sw, vhp + o);
            cp16(st + 24576 + sw, vlp + o);
        }
        CP_COMMIT();
    };
    const int ntiles = seq >> 6;
    load_kv(0, 0);
    if (ntiles > 1) load_kv(1, 1);

    CP_WAIT(1);
    __syncthreads();

    uint32_t qfh[4][4], qfl[4][4];
    {
        const int arow = wid*16 + (lane & 15);
        #pragma unroll
        for (int ks = 0; ks < 4; ks++) {
            const uint32_t off = SWZ((uint32_t)(arow*128 + ks*32 + ((lane >> 4) & 1)*16));
            ldsm4(qfh[ks][0], qfh[ks][1], qfh[ks][2], qfh[ks][3], db + off);
            ldsm4(qfl[ks][0], qfl[ks][1], qfl[ks][2], qfl[ks][3], db + 8192 + off);
        }
    }

    float m0 = -1e30f, m1 = -1e30f, l0 = 0.f, l1 = 0.f;
    float oacc[8][4];
    #pragma unroll
    for (int nt = 0; nt < 8; nt++)
        #pragma unroll
        for (int i = 0; i < 4; i++) oacc[nt][i] = 0.f;

    for (int kt = 0; kt < ntiles; kt++) {
        if (kt > 0) {
            if (kt + 1 < ntiles) { CP_WAIT(1); } else { CP_WAIT(0); }
            __syncthreads();
        }
        const uint32_t st = kvb + (kt & 1)*FSTG;

        float sacc[8][4];
        #pragma unroll
        for (int nt = 0; nt < 8; nt++)
            #pragma unroll
            for (int i = 0; i < 4; i++) sacc[nt][i] = 0.f;

        #pragma unroll
        for (int ks = 0; ks < 4; ks++) {
            const uint32_t cb = (uint32_t)(ks*32 + ((lane >> 4) & 1)*16);
            uint32_t b_h[8][2], b_l[8][2];
            #pragma unroll
            for (int np = 0; np < 4; np++) {
                const uint32_t off = SWZ((uint32_t)((np*16 + (lane & 15))*128) + cb);
                uint32_t r0, r1, r2, r3;
                ldsm4(r0, r1, r2, r3, st + off);
                b_h[np*2][0] = r0; b_h[np*2][1] = r2;
                b_h[np*2+1][0] = r1; b_h[np*2+1][1] = r3;
                ldsm4(r0, r1, r2, r3, st + 8192 + off);
                b_l[np*2][0] = r0; b_l[np*2][1] = r2;
                b_l[np*2+1][0] = r1; b_l[np*2+1][1] = r3;
            }
            #pragma unroll
            for (int nt = 0; nt < 8; nt++) {
                mma_bf16(sacc[nt], qfh[ks], b_h[nt]);
                mma_bf16(sacc[nt], qfh[ks], b_l[nt]);
                mma_bf16(sacc[nt], qfl[ks], b_h[nt]);
            }
        }

        float rx0 = -1e30f, rx1 = -1e30f;
        #pragma unroll
        for (int nt = 0; nt < 8; nt++) {
            #pragma unroll
            for (int i = 0; i < 4; i++) sacc[nt][i] *= SCALE;
            rx0 = fmaxf(rx0, fmaxf(sacc[nt][0], sacc[nt][1]));
            rx1 = fmaxf(rx1, fmaxf(sacc[nt][2], sacc[nt][3]));
        }
        #pragma unroll
        for (int off = 1; off <= 2; off <<= 1) {
            rx0 = fmaxf(rx0, __shfl_xor_sync(0xffffffffu, rx0, off));
            rx1 = fmaxf(rx1, __shfl_xor_sync(0xffffffffu, rx1, off));
        }
        const float mn0 = fmaxf(m0, rx0), mn1 = fmaxf(m1, rx1);
        const float cr0 = __expf(m0 - mn0), cr1 = __expf(m1 - mn1);
        float rs0 = 0.f, rs1 = 0.f;
        #pragma unroll
        for (int nt = 0; nt < 8; nt++) {
            sacc[nt][0] = __expf(sacc[nt][0] - mn0);
            sacc[nt][1] = __expf(sacc[nt][1] - mn0);
            sacc[nt][2] = __expf(sacc[nt][2] - mn1);
            sacc[nt][3] = __expf(sacc[nt][3] - mn1);
            rs0 += sacc[nt][0] + sacc[nt][1];
            rs1 += sacc[nt][2] + sacc[nt][3];
        }
        #pragma unroll
        for (int off = 1; off <= 2; off <<= 1) {
            rs0 += __shfl_xor_sync(0xffffffffu, rs0, off);
            rs1 += __shfl_xor_sync(0xffffffffu, rs1, off);
        }
        l0 = l0*cr0 + rs0; l1 = l1*cr1 + rs1;
        m0 = mn0; m1 = mn1;
        #pragma unroll
        for (int nt = 0; nt < 8; nt++) {
            oacc[nt][0] *= cr0; oacc[nt][1] *= cr0;
            oacc[nt][2] *= cr1; oacc[nt][3] *= cr1;
        }

        #pragma unroll
        for (int j = 0; j < 4; j++) {
            uint32_t pa_h[4], pa_l[4];
            split_pack(sacc[2*j][0],   sacc[2*j][1],   pa_h[0], pa_l[0]);
            split_pack(sacc[2*j][2],   sacc[2*j][3],   pa_h[1], pa_l[1]);
            split_pack(sacc[2*j+1][0], sacc[2*j+1][1], pa_h[2], pa_l[2]);
            split_pack(sacc[2*j+1][2], sacc[2*j+1][3], pa_h[3], pa_l[3]);

            uint32_t v_h[8][2], v_l[8][2];
            const int srow = j*16 + (lane & 15);
            #pragma unroll
            for (int np = 0; np < 4; np++) {
                const uint32_t off = SWZ((uint32_t)(srow*128 + np*32 + ((lane >> 4) & 1)*16));
                uint32_t r0, r1, r2, r3;
                ldsm4t(r0, r1, r2, r3, st + 16384 + off);
                v_h[np*2][0] = r0; v_h[np*2][1] = r1;
                v_h[np*2+1][0] = r2; v_h[np*2+1][1] = r3;
                ldsm4t(r0, r1, r2, r3, st + 24576 + off);
                v_l[np*2][0] = r0; v_l[np*2][1] = r1;
                v_l[np*2+1][0] = r2; v_l[np*2+1][1] = r3;
            }
            #pragma unroll
            for (int nt = 0; nt < 8; nt++) {
                mma_bf16(oacc[nt], pa_h, v_h[nt]);
                mma_bf16(oacc[nt], pa_h, v_l[nt]);
                mma_bf16(oacc[nt], pa_l, v_h[nt]);
            }
        }
        __syncthreads();
        if (kt + 2 < ntiles) load_kv(kt + 2, kt & 1);
    }

    const float inv0 = 1.f / l0, inv1 = 1.f / l1;
    const int rr = lane >> 2, cc = (lane & 3)*2;
    const size_t row0 = bo + qt*64 + wid*16 + rr;
    #pragma unroll
    for (int nt = 0; nt < 8; nt++) {
        const int col = head*64 + nt*8 + cc;
        uint32_t hi, lo;
        split_pack(oacc[nt][0]*inv0, oacc[nt][1]*inv0, hi, lo);
        *reinterpret_cast<uint32_t*>(&Oh[row0*ors + col]) = hi;
        *reinterpret_cast<uint32_t*>(&Ol[row0*ors + col]) = lo;
        split_pack(oacc[nt][2]*inv1, oacc[nt][3]*inv1, hi, lo);
        *reinterpret_cast<uint32_t*>(&Oh[(row0+8)*ors + col]) = hi;
        *reinterpret_cast<uint32_t*>(&Ol[(row0+8)*ors + col]) = lo;
    }
}

// ---------------- launch ----------------
extern "C" void kernel_launch(void* const* d_in, const int* in_sizes, int n_in,
                              void* d_out, int out_size)
{
    const float* x         = (const float*)d_in[0];
    const float* pos_emb   = (const float*)d_in[1];
    const float* l_q_w     = (const float*)d_in[2];
    const float* l_kv_w    = (const float*)d_in[3];
    const float* l_proj_w  = (const float*)d_in[4];
    const float* l_proj_b  = (const float*)d_in[5];
    const float* h_qkv_w   = (const float*)d_in[6];
    const float* h_proj_w  = (const float*)d_in[7];
    const float* h_proj_b  = (const float*)d_in[8];
    const float* in_proj_w = (const float*)d_in[9];
    const float* in_proj_b = (const float*)d_in[10];
    const float* out_proj_w= (const float*)d_in[11];
    const float* out_proj_b= (const float*)d_in[12];
    float* out = (float*)d_out;

    __nv_bfloat16 *cth,*ctl,*xph,*xpl,*qmh,*qml;
    __nv_bfloat16 *hh,*hl,*lh,*ll,*yh,*yl,*mh,*ml;
    __nv_bfloat16 *wch,*wcl,*w3h,*w3l,*w4h,*w4l,*w5h,*w5l,*w6h,*w6l;
    cudaGetSymbolAddress((void**)&cth, g_cat_h);  cudaGetSymbolAddress((void**)&ctl, g_cat_l);
    cudaGetSymbolAddress((void**)&xph, g_xp_h);   cudaGetSymbolAddress((void**)&xpl, g_xp_l);
    cudaGetSymbolAddress((void**)&qmh, g_qm_h);   cudaGetSymbolAddress((void**)&qml, g_qm_l);
    cudaGetSymbolAddress((void**)&hh,  g_hifi_h); cudaGetSymbolAddress((void**)&hl,  g_hifi_l);
    cudaGetSymbolAddress((void**)&lh,  g_lofi_h); cudaGetSymbolAddress((void**)&ll,  g_lofi_l);
    cudaGetSymbolAddress((void**)&yh,  g_y_h);    cudaGetSymbolAddress((void**)&yl,  g_y_l);
    cudaGetSymbolAddress((void**)&mh,  g_mha_h);  cudaGetSymbolAddress((void**)&ml,  g_mha_l);
    cudaGetSymbolAddress((void**)&wch, g_wch);    cudaGetSymbolAddress((void**)&wcl, g_wcl);
    cudaGetSymbolAddress((void**)&w3h, g_w3h);    cudaGetSymbolAddress((void**)&w3l, g_w3l);
    cudaGetSymbolAddress((void**)&w4h, g_w4h);    cudaGetSymbolAddress((void**)&w4l, g_w4l);
    cudaGetSymbolAddress((void**)&w5h, g_w5h);    cudaGetSymbolAddress((void**)&w5l, g_w5l);
    cudaGetSymbolAddress((void**)&w6h, g_w6h);    cudaGetSymbolAddress((void**)&w6l, g_w6l);

    cudaFuncSetAttribute(gemm_mma_kernel,  cudaFuncAttributeMaxDynamicSharedMemorySize, GEMM_SMEM);
    cudaFuncSetAttribute(flash_mma_kernel, cudaFuncAttributeMaxDynamicSharedMemorySize, FLASH_SMEM);

    const int M = MTOT;
    const dim3 wb(32, 8);

    add_pos_split_kernel<<<(M*CDIM/4 + 255)/256, 256>>>(x, pos_emb, xph, xpl);

    // weight cat: rows 0-767 h_qkv, 768-1023 l_q, 1024-1535 l_kv
    wsplit_kernel<<<dim3(768/32, 512/32),  wb>>>(h_qkv_w,   wch,            wcl,            512, 768);
    wsplit_kernel<<<dim3(256/32, 512/32),  wb>>>(l_q_w,     wch + 768*512,  wcl + 768*512,  512, 256);
    wsplit_kernel<<<dim3(512/32, 512/32),  wb>>>(l_kv_w,    wch + 1024*512, wcl + 1024*512, 512, 512);
    wsplit_kernel<<<dim3(256/32, 256/32),  wb>>>(h_proj_w,  w3h, w3l, 256, 256);
    wsplit_kernel<<<dim3(256/32, 256/32),  wb>>>(l_proj_w,  w4h, w4l, 256, 256);
    wsplit_kernel<<<dim3(1536/32, 512/32), wb>>>(in_proj_w, w5h, w5l, 512, 1536);
    wsplit_kernel<<<dim3(512/32, 512/32),  wb>>>(out_proj_w,w6h, w6l, 512, 512);

    // merged input projection: cat = [hifi qkv | l_q | l_k | l_v]
    gemm_mma_kernel<<<dim3(1536/64, M/128), 256, GEMM_SMEM>>>(
        xph, xpl, wch, wcl, nullptr, nullptr, cth, ctl, 1536, 512, 1536);

    // attention branches
    hifi_attn_kernel<<<4096, 128>>>(cth, ctl, hh, hl);
    flash_mma_kernel<<<dim3(SEQ/64, 4, BATCH), 128, FLASH_SMEM>>>(
        cth + 768, ctl + 768, cth + 1024, ctl + 1024, cth + 1280, ctl + 1280,
        lh, ll, 1536, 1536, 256, SEQ);

    // branch projections -> split y
    gemm_mma_kernel<<<dim3(256/64, M/128), 256, GEMM_SMEM>>>(
        hh, hl, w3h, w3l, h_proj_b, nullptr, yh,       yl,       256, 256, 512);
    gemm_mma_kernel<<<dim3(256/64, M/128), 256, GEMM_SMEM>>>(
        lh, ll, w4h, w4l, l_proj_b, nullptr, yh + 256, yl + 256, 256, 256, 512);

    // final MHA
    gemm_mma_kernel<<<dim3(1536/64, M/128), 256, GEMM_SMEM>>>(
        yh, yl, w5h, w5l, in_proj_b, nullptr, qmh, qml, 1536, 512, 1536);
    flash_mma_kernel<<<dim3(SEQ/64, 8, BATCH), 128, FLASH_SMEM>>>(
        qmh, qml, qmh + 512, qml + 512, qmh + 1024, qml + 1024, mh, ml, 1536, 1536, 512, SEQ);
    gemm_mma_kernel<<<dim3(512/64, M/128), 256, GEMM_SMEM>>>(
        mh, ml, w6h, w6l, out_proj_b, out, nullptr, nullptr, 512, 512, 512);
}

// round 7
// speedup vs baseline: 5.2671x; 1.0021x over previous
#include <cuda_runtime.h>
#include <cuda_bf16.h>
#include <math.h>
#include <stdint.h>

#define BATCH 16
#define SEQ   1024
#define CDIM  512
#define SCALE 0.125f
#define MTOT  (BATCH*SEQ)

// ---------------- scratch ----------------
__device__ __nv_bfloat16 g_cat_h[MTOT*1536], g_cat_l[MTOT*1536];  // [hifi qkv | l_q | l_k | l_v]
__device__ __nv_bfloat16 g_qm_h [MTOT*1536], g_qm_l [MTOT*1536];
__device__ __nv_bfloat16 g_xp_h [MTOT*CDIM], g_xp_l [MTOT*CDIM];
__device__ __nv_bfloat16 g_hifi_h[MTOT*256], g_hifi_l[MTOT*256];
__device__ __nv_bfloat16 g_lofi_h[MTOT*256], g_lofi_l[MTOT*256];
__device__ __nv_bfloat16 g_y_h  [MTOT*512],  g_y_l  [MTOT*512];
__device__ __nv_bfloat16 g_mha_h[MTOT*512],  g_mha_l[MTOT*512];
__device__ __nv_bfloat16 g_wch[1536*512], g_wcl[1536*512];        // cat weights^T
__device__ __nv_bfloat16 g_w3h[256*256],  g_w3l[256*256];
__device__ __nv_bfloat16 g_w4h[256*256],  g_w4l[256*256];
__device__ __nv_bfloat16 g_w5h[1536*512], g_w5l[1536*512];
__device__ __nv_bfloat16 g_w6h[512*512],  g_w6l[512*512];

// ---------------- helpers ----------------
__device__ __forceinline__ uint32_t s2u(const void* p) {
    return (uint32_t)__cvta_generic_to_shared(p);
}
#define SWZ(o) ((o) ^ (((o) >> 3) & 0x70))

__device__ __forceinline__ void cp16(uint32_t smem, const void* g) {
    asm volatile("cp.async.cg.shared.global [%0], [%1], 16;"
                 :: "r"(smem), "l"(__cvta_generic_to_global(g)));
}
#define CP_COMMIT() asm volatile("cp.async.commit_group;" ::: "memory")
#define CP_WAIT(n)  asm volatile("cp.async.wait_group %0;" :: "n"(n) : "memory")

__device__ __forceinline__ void ldsm4(uint32_t& r0, uint32_t& r1, uint32_t& r2, uint32_t& r3,
                                      uint32_t a) {
    asm volatile("ldmatrix.sync.aligned.m8n8.x4.shared.b16 {%0,%1,%2,%3}, [%4];"
                 : "=r"(r0), "=r"(r1), "=r"(r2), "=r"(r3) : "r"(a));
}
__device__ __forceinline__ void ldsm4t(uint32_t& r0, uint32_t& r1, uint32_t& r2, uint32_t& r3,
                                       uint32_t a) {
    asm volatile("ldmatrix.sync.aligned.m8n8.x4.trans.shared.b16 {%0,%1,%2,%3}, [%4];"
                 : "=r"(r0), "=r"(r1), "=r"(r2), "=r"(r3) : "r"(a));
}
__device__ __forceinline__ void mma_bf16(float* d, const uint32_t* a, const uint32_t* b) {
    asm volatile("mma.sync.aligned.m16n8k16.row.col.f32.bf16.bf16.f32 "
                 "{%0,%1,%2,%3}, {%4,%5,%6,%7}, {%8,%9}, {%0,%1,%2,%3};"
                 : "+f"(d[0]), "+f"(d[1]), "+f"(d[2]), "+f"(d[3])
                 : "r"(a[0]), "r"(a[1]), "r"(a[2]), "r"(a[3]), "r"(b[0]), "r"(b[1]));
}

__device__ __forceinline__ void split2(float x, __nv_bfloat16& h, __nv_bfloat16& l) {
    h = __float2bfloat16_rn(x);
    l = __float2bfloat16_rn(x - __bfloat162float(h));
}
__device__ __forceinline__ void split_pack(float x, float y, uint32_t& hi, uint32_t& lo) {
    __nv_bfloat162 h2, l2;
    split2(x, h2.x, l2.x);
    split2(y, h2.y, l2.y);
    hi = *reinterpret_cast<uint32_t*>(&h2);
    lo = *reinterpret_cast<uint32_t*>(&l2);
}

// ---------------- x + pos -> hi/lo split ----------------
__global__ __launch_bounds__(256) void add_pos_split_kernel(
    const float* __restrict__ x, const float* __restrict__ pos,
    __nv_bfloat16* __restrict__ oh, __nv_bfloat16* __restrict__ ol)
{
    const int per_b4 = SEQ*CDIM/4;
    int i = blockIdx.x * blockDim.x + threadIdx.x;
    float4 a = reinterpret_cast<const float4*>(x)[i];
    float4 p = reinterpret_cast<const float4*>(pos)[i % per_b4];
    __nv_bfloat162 h01, h23, l01, l23;
    split2(a.x+p.x, h01.x, l01.x); split2(a.y+p.y, h01.y, l01.y);
    split2(a.z+p.z, h23.x, l23.x); split2(a.w+p.w, h23.y, l23.y);
    *reinterpret_cast<__nv_bfloat162*>(&oh[i*4])   = h01;
    *reinterpret_cast<__nv_bfloat162*>(&oh[i*4+2]) = h23;
    *reinterpret_cast<__nv_bfloat162*>(&ol[i*4])   = l01;
    *reinterpret_cast<__nv_bfloat162*>(&ol[i*4+2]) = l23;
}

// ---------------- weight transpose + split: W[K][N] -> T[N][K] ----------------
__global__ __launch_bounds__(256) void wsplit_kernel(
    const float* __restrict__ W, __nv_bfloat16* __restrict__ Th,
    __nv_bfloat16* __restrict__ Tl, int K, int N)
{
    __shared__ float ts[32][33];
    const int n0 = blockIdx.x*32, k0 = blockIdx.y*32;
    const int x = threadIdx.x, y = threadIdx.y;
    #pragma unroll
    for (int r = 0; r < 4; r++)
        ts[y + r*8][x] = W[(size_t)(k0 + y + r*8)*N + n0 + x];
    __syncthreads();
    #pragma unroll
    for (int r = 0; r < 4; r++) {
        __nv_bfloat16 h, l;
        split2(ts[x][y + r*8], h, l);
        size_t o = (size_t)(n0 + y + r*8)*K + k0 + x;
        Th[o] = h; Tl[o] = l;
    }
}

// ---------------- HMMA split-bf16 GEMM (shared body) ----------------
// C[M,N] = (Ah+Al)[M,K] @ (Bh+Bl)[N,K]^T + bias; out fp32 (Cf) or split (Ch/Cl)
// BM=128, BN=64, BK=64, 256 threads (8 warps: 4 M x 2 N), 2-stage cp.async.
#define GSTG 49152
#define GEMM_SMEM (1024 + 2*GSTG)

__device__ __forceinline__ void gemm_body(
    const __nv_bfloat16* __restrict__ Ah, const __nv_bfloat16* __restrict__ Al,
    const __nv_bfloat16* __restrict__ Bh, const __nv_bfloat16* __restrict__ Bl,
    const float* __restrict__ bias, float* __restrict__ Cf,
    __nv_bfloat16* __restrict__ Ch, __nv_bfloat16* __restrict__ Cl,
    int N, int K, int ldc, char* smem)
{
    const uint32_t sb = s2u(smem);
    const uint32_t db = (sb + 1023u) & ~1023u;
    const int tid = threadIdx.x, wid = tid >> 5, lane = tid & 31;
    const int m0 = blockIdx.y*128, n0 = blockIdx.x*64;
    const int wm = (wid & 3)*32, wn = (wid >> 2)*32;

    float acc[2][4][4];
    #pragma unroll
    for (int mt = 0; mt < 2; mt++)
        #pragma unroll
        for (int nt = 0; nt < 4; nt++)
            #pragma unroll
            for (int i = 0; i < 4; i++) acc[mt][nt][i] = 0.f;

    const int r8 = tid >> 3, seg = tid & 7;
    auto load = [&](int c, int s) {
        const int k0 = c*64;
        const uint32_t st = db + s*GSTG;
        #pragma unroll
        for (int i = 0; i < 4; i++) {
            const int rr = r8 + 32*i;
            const uint32_t sw = SWZ((uint32_t)(rr*128 + seg*16));
            const size_t ao = (size_t)(m0 + rr)*K + k0 + seg*8;
            cp16(st + sw,         Ah + ao);
            cp16(st + 16384 + sw, Al + ao);
        }
        #pragma unroll
        for (int i = 0; i < 2; i++) {
            const int rr = r8 + 32*i;
            const uint32_t sw = SWZ((uint32_t)(rr*128 + seg*16));
            const size_t bo = (size_t)(n0 + rr)*K + k0 + seg*8;
            cp16(st + 32768 + sw, Bh + bo);
            cp16(st + 40960 + sw, Bl + bo);
        }
        CP_COMMIT();
    };

    const int nch = K / 64;
    load(0, 0);
    if (nch > 1) load(1, 1);

    for (int c = 0; c < nch; c++) {
        const int s = c & 1;
        if (c + 1 < nch) { CP_WAIT(1); } else { CP_WAIT(0); }
        __syncthreads();
        const uint32_t ab = db + s*GSTG, bb = ab + 32768;

        #pragma unroll
        for (int ks = 0; ks < 4; ks++) {
            const uint32_t cb = (uint32_t)(ks*32 + ((lane >> 4) & 1)*16);
            uint32_t a_h[2][4], a_l[2][4], b_h[4][2], b_l[4][2];
            #pragma unroll
            for (int mt = 0; mt < 2; mt++) {
                const uint32_t off = SWZ((uint32_t)((wm + mt*16 + (lane & 15))*128) + cb);
                ldsm4(a_h[mt][0], a_h[mt][1], a_h[mt][2], a_h[mt][3], ab + off);
                ldsm4(a_l[mt][0], a_l[mt][1], a_l[mt][2], a_l[mt][3], ab + 16384 + off);
            }
            #pragma unroll
            for (int np = 0; np < 2; np++) {
                const uint32_t off = SWZ((uint32_t)((wn + np*16 + (lane & 15))*128) + cb);
                uint32_t r0, r1, r2, r3;
                ldsm4(r0, r1, r2, r3, bb + off);
                b_h[np*2][0] = r0; b_h[np*2][1] = r2;
                b_h[np*2+1][0] = r1; b_h[np*2+1][1] = r3;
                ldsm4(r0, r1, r2, r3, bb + 8192 + off);
                b_l[np*2][0] = r0; b_l[np*2][1] = r2;
                b_l[np*2+1][0] = r1; b_l[np*2+1][1] = r3;
            }
            #pragma unroll
            for (int mt = 0; mt < 2; mt++)
                #pragma unroll
                for (int nt = 0; nt < 4; nt++) {
                    mma_bf16(acc[mt][nt], a_h[mt], b_h[nt]);
                    mma_bf16(acc[mt][nt], a_h[mt], b_l[nt]);
                    mma_bf16(acc[mt][nt], a_l[mt], b_h[nt]);
                }
        }
        __syncthreads();
        if (c + 2 < nch) load(c + 2, s);
    }

    const int rr = lane >> 2, cc = (lane & 3)*2;
    #pragma unroll
    for (int mt = 0; mt < 2; mt++)
        #pragma unroll
        for (int nt = 0; nt < 4; nt++) {
            const int row = m0 + wm + mt*16 + rr;
            const int col = n0 + wn + nt*8 + cc;
            float b0 = bias ? bias[col] : 0.f, b1 = bias ? bias[col+1] : 0.f;
            float v00 = acc[mt][nt][0] + b0, v01 = acc[mt][nt][1] + b1;
            float v10 = acc[mt][nt][2] + b0, v11 = acc[mt][nt][3] + b1;
            if (Cf) {
                *reinterpret_cast<float2*>(&Cf[(size_t)row*ldc + col])     = make_float2(v00, v01);
                *reinterpret_cast<float2*>(&Cf[(size_t)(row+8)*ldc + col]) = make_float2(v10, v11);
            } else {
                uint32_t hi, lo;
                split_pack(v00, v01, hi, lo);
                *reinterpret_cast<uint32_t*>(&Ch[(size_t)row*ldc + col]) = hi;
                *reinterpret_cast<uint32_t*>(&Cl[(size_t)row*ldc + col]) = lo;
                split_pack(v10, v11, hi, lo);
                *reinterpret_cast<uint32_t*>(&Ch[(size_t)(row+8)*ldc + col]) = hi;
                *reinterpret_cast<uint32_t*>(&Cl[(size_t)(row+8)*ldc + col]) = lo;
            }
        }
}

__global__ __launch_bounds__(256, 2) void gemm_mma_kernel(
    const __nv_bfloat16* __restrict__ Ah, const __nv_bfloat16* __restrict__ Al,
    const __nv_bfloat16* __restrict__ Bh, const __nv_bfloat16* __restrict__ Bl,
    const float* __restrict__ bias, float* __restrict__ Cf,
    __nv_bfloat16* __restrict__ Ch, __nv_bfloat16* __restrict__ Cl,
    int N, int K, int ldc)
{
    extern __shared__ char smem[];
    gemm_body(Ah, Al, Bh, Bl, bias, Cf, Ch, Cl, N, K, ldc, smem);
}

// two independent same-shape GEMMs in one launch (blockIdx.z selects)
__global__ __launch_bounds__(256, 2) void gemm_mma_dual_kernel(
    const __nv_bfloat16* A1h, const __nv_bfloat16* A1l,
    const __nv_bfloat16* B1h, const __nv_bfloat16* B1l,
    const float* bias1, __nv_bfloat16* C1h, __nv_bfloat16* C1l,
    const __nv_bfloat16* A2h, const __nv_bfloat16* A2l,
    const __nv_bfloat16* B2h, const __nv_bfloat16* B2l,
    const float* bias2, __nv_bfloat16* C2h, __nv_bfloat16* C2l,
    int N, int K, int ldc)
{
    extern __shared__ char smem[];
    if (blockIdx.z == 0)
        gemm_body(A1h, A1l, B1h, B1l, bias1, nullptr, C1h, C1l, N, K, ldc, smem);
    else
        gemm_body(A2h, A2l, B2h, B2l, bias2, nullptr, C2h, C2l, N, K, ldc, smem);
}

// ---------------- hifi 2x2 window attention (split bf16 in/out) ----------------
__global__ __launch_bounds__(128) void hifi_attn_kernel(
    const __nv_bfloat16* __restrict__ ch, const __nv_bfloat16* __restrict__ cl,
    __nv_bfloat16* __restrict__ oh, __nv_bfloat16* __restrict__ ol)
{
    const int warp = threadIdx.x >> 5, lane = threadIdx.x & 31;
    const int unit = blockIdx.x * 4 + warp;
    const int head = unit & 3, g = (unit >> 2) & 255, b = unit >> 10;
    const int gi = g >> 4, gj = g & 15;

    int n[4];
    #pragma unroll
    for (int t = 0; t < 4; t++)
        n[t] = (gi*2 + (t>>1)) * 32 + gj*2 + (t&1);

    float q[4][2], k[4][2], v[4][2];
    #pragma unroll
    for (int t = 0; t < 4; t++) {
        const size_t p = (size_t)(b*SEQ + n[t]) * 1536 + head*64;
        q[t][0] = __bfloat162float(ch[p+lane])        + __bfloat162float(cl[p+lane]);
        q[t][1] = __bfloat162float(ch[p+lane+32])     + __bfloat162float(cl[p+lane+32]);
        k[t][0] = __bfloat162float(ch[p+256+lane])    + __bfloat162float(cl[p+256+lane]);
        k[t][1] = __bfloat162float(ch[p+256+lane+32]) + __bfloat162float(cl[p+256+lane+32]);
        v[t][0] = __bfloat162float(ch[p+512+lane])    + __bfloat162float(cl[p+512+lane]);
        v[t][1] = __bfloat162float(ch[p+512+lane+32]) + __bfloat162float(cl[p+512+lane+32]);
    }
    float s[4][4];
    #pragma unroll
    for (int t = 0; t < 4; t++)
        #pragma unroll
        for (int u = 0; u < 4; u++)
            s[t][u] = q[t][0]*k[u][0] + q[t][1]*k[u][1];
    #pragma unroll
    for (int off = 16; off >= 1; off >>= 1)
        #pragma unroll
        for (int t = 0; t < 4; t++)
            #pragma unroll
            for (int u = 0; u < 4; u++)
                s[t][u] += __shfl_xor_sync(0xffffffffu, s[t][u], off);
    #pragma unroll
    for (int t = 0; t < 4; t++) {
        float s0=s[t][0]*SCALE, s1=s[t][1]*SCALE, s2=s[t][2]*SCALE, s3=s[t][3]*SCALE;
        float mx = fmaxf(fmaxf(s0,s1), fmaxf(s2,s3));
        float e0=__expf(s0-mx), e1=__expf(s1-mx), e2=__expf(s2-mx), e3=__expf(s3-mx);
        float inv = 1.f/(e0+e1+e2+e3);
        e0*=inv; e1*=inv; e2*=inv; e3*=inv;
        float o0 = e0*v[0][0]+e1*v[1][0]+e2*v[2][0]+e3*v[3][0];
        float o1 = e0*v[0][1]+e1*v[1][1]+e2*v[2][1]+e3*v[3][1];
        size_t base = (size_t)(b*SEQ + n[t]) * 256 + head*64;
        __nv_bfloat16 h, l;
        split2(o0,h,l); oh[base+lane]=h;    ol[base+lane]=l;
        split2(o1,h,l); oh[base+lane+32]=h; ol[base+lane+32]=l;
    }
}

// ---------------- HMMA flash attention ----------------
#define FSTG 32768
#define FLASH_SMEM (1024 + 16384 + 2*FSTG)

__global__ __launch_bounds__(128, 1) void flash_mma_kernel(
    const __nv_bfloat16* __restrict__ Qh, const __nv_bfloat16* __restrict__ Ql,
    const __nv_bfloat16* __restrict__ Kh, const __nv_bfloat16* __restrict__ Kl,
    const __nv_bfloat16* __restrict__ Vh, const __nv_bfloat16* __restrict__ Vl,
    __nv_bfloat16* __restrict__ Oh, __nv_bfloat16* __restrict__ Ol,
    int qrs, int krs, int ors, int seq)
{
    extern __shared__ char smem[];
    const uint32_t sb = s2u(smem);
    const uint32_t db = (sb + 1023u) & ~1023u;
    const int tid = threadIdx.x, wid = tid >> 5, lane = tid & 31;
    const int b = blockIdx.z, head = blockIdx.y, qt = blockIdx.x;
    const size_t bo = (size_t)b * seq;

    const __nv_bfloat16* qhp = Qh + (bo + qt*64)*qrs + head*64;
    const __nv_bfloat16* qlp = Ql + (bo + qt*64)*qrs + head*64;
    const __nv_bfloat16* khp = Kh + bo*krs + head*64;
    const __nv_bfloat16* klp = Kl + bo*krs + head*64;
    const __nv_bfloat16* vhp = Vh + bo*krs + head*64;
    const __nv_bfloat16* vlp = Vl + bo*krs + head*64;

    const int r8 = tid >> 3, seg = tid & 7;

    #pragma unroll
    for (int i = 0; i < 4; i++) {
        const int rr = r8 + 16*i;
        const uint32_t sw = SWZ((uint32_t)(rr*128 + seg*16));
        cp16(db + sw,        qhp + (size_t)rr*qrs + seg*8);
        cp16(db + 8192 + sw, qlp + (size_t)rr*qrs + seg*8);
    }
    CP_COMMIT();

    const uint32_t kvb = db + 16384;
    auto load_kv = [&](int kt, int s) {
        const uint32_t st = kvb + s*FSTG;
        const size_t rb = (size_t)kt * 64;
        #pragma unroll
        for (int i = 0; i < 4; i++) {
            const int rr = r8 + 16*i;
            const uint32_t sw = SWZ((uint32_t)(rr*128 + seg*16));
            const size_t o = (rb + rr)*krs + seg*8;
            cp16(st + sw,         khp + o);
            cp16(st + 8192 + sw,  klp + o);
            cp16(st + 16384 + sw, vhp + o);
            cp16(st + 24576 + sw, vlp + o);
        }
        CP_COMMIT();
    };
    const int ntiles = seq >> 6;
    load_kv(0, 0);
    if (ntiles > 1) load_kv(1, 1);

    CP_WAIT(1);
    __syncthreads();

    uint32_t qfh[4][4], qfl[4][4];
    {
        const int arow = wid*16 + (lane & 15);
        #pragma unroll
        for (int ks = 0; ks < 4; ks++) {
            const uint32_t off = SWZ((uint32_t)(arow*128 + ks*32 + ((lane >> 4) & 1)*16));
            ldsm4(qfh[ks][0], qfh[ks][1], qfh[ks][2], qfh[ks][3], db + off);
            ldsm4(qfl[ks][0], qfl[ks][1], qfl[ks][2], qfl[ks][3], db + 8192 + off);
        }
    }

    float m0 = -1e30f, m1 = -1e30f, l0 = 0.f, l1 = 0.f;
    float oacc[8][4];
    #pragma unroll
    for (int nt = 0; nt < 8; nt++)
        #pragma unroll
        for (int i = 0; i < 4; i++) oacc[nt][i] = 0.f;

    for (int kt = 0; kt < ntiles; kt++) {
        if (kt > 0) {
            if (kt + 1 < ntiles) { CP_WAIT(1); } else { CP_WAIT(0); }
            __syncthreads();
        }
        const uint32_t st = kvb + (kt & 1)*FSTG;

        float sacc[8][4];
        #pragma unroll
        for (int nt = 0; nt < 8; nt++)
            #pragma unroll
            for (int i = 0; i < 4; i++) sacc[nt][i] = 0.f;

        #pragma unroll
        for (int ks = 0; ks < 4; ks++) {
            const uint32_t cb = (uint32_t)(ks*32 + ((lane >> 4) & 1)*16);
            uint32_t b_h[8][2], b_l[8][2];
            #pragma unroll
            for (int np = 0; np < 4; np++) {
                const uint32_t off = SWZ((uint32_t)((np*16 + (lane & 15))*128) + cb);
                uint32_t r0, r1, r2, r3;
                ldsm4(r0, r1, r2, r3, st + off);
                b_h[np*2][0] = r0; b_h[np*2][1] = r2;
                b_h[np*2+1][0] = r1; b_h[np*2+1][1] = r3;
                ldsm4(r0, r1, r2, r3, st + 8192 + off);
                b_l[np*2][0] = r0; b_l[np*2][1] = r2;
                b_l[np*2+1][0] = r1; b_l[np*2+1][1] = r3;
            }
            #pragma unroll
            for (int nt = 0; nt < 8; nt++) {
                mma_bf16(sacc[nt], qfh[ks], b_h[nt]);
                mma_bf16(sacc[nt], qfh[ks], b_l[nt]);
                mma_bf16(sacc[nt], qfl[ks], b_h[nt]);
            }
        }

        float rx0 = -1e30f, rx1 = -1e30f;
        #pragma unroll
        for (int nt = 0; nt < 8; nt++) {
            #pragma unroll
            for (int i = 0; i < 4; i++) sacc[nt][i] *= SCALE;
            rx0 = fmaxf(rx0, fmaxf(sacc[nt][0], sacc[nt][1]));
            rx1 = fmaxf(rx1, fmaxf(sacc[nt][2], sacc[nt][3]));
        }
        #pragma unroll
        for (int off = 1; off <= 2; off <<= 1) {
            rx0 = fmaxf(rx0, __shfl_xor_sync(0xffffffffu, rx0, off));
            rx1 = fmaxf(rx1, __shfl_xor_sync(0xffffffffu, rx1, off));
        }
        const float mn0 = fmaxf(m0, rx0), mn1 = fmaxf(m1, rx1);
        const float cr0 = __expf(m0 - mn0), cr1 = __expf(m1 - mn1);
        float rs0 = 0.f, rs1 = 0.f;
        #pragma unroll
        for (int nt = 0; nt < 8; nt++) {
            sacc[nt][0] = __expf(sacc[nt][0] - mn0);
            sacc[nt][1] = __expf(sacc[nt][1] - mn0);
            sacc[nt][2] = __expf(sacc[nt][2] - mn1);
            sacc[nt][3] = __expf(sacc[nt][3] - mn1);
            rs0 += sacc[nt][0] + sacc[nt][1];
            rs1 += sacc[nt][2] + sacc[nt][3];
        }
        #pragma unroll
        for (int off = 1; off <= 2; off <<= 1) {
            rs0 += __shfl_xor_sync(0xffffffffu, rs0, off);
            rs1 += __shfl_xor_sync(0xffffffffu, rs1, off);
        }
        l0 = l0*cr0 + rs0; l1 = l1*cr1 + rs1;
        m0 = mn0; m1 = mn1;
        #pragma unroll
        for (int nt = 0; nt < 8; nt++) {
            oacc[nt][0] *= cr0; oacc[nt][1] *= cr0;
            oacc[nt][2] *= cr1; oacc[nt][3] *= cr1;
        }

        #pragma unroll
        for (int j = 0; j < 4; j++) {
            uint32_t pa_h[4], pa_l[4];
            split_pack(sacc[2*j][0],   sacc[2*j][1],   pa_h[0], pa_l[0]);
            split_pack(sacc[2*j][2],   sacc[2*j][3],   pa_h[1], pa_l[1]);
            split_pack(sacc[2*j+1][0], sacc[2*j+1][1], pa_h[2], pa_l[2]);
            split_pack(sacc[2*j+1][2], sacc[2*j+1][3], pa_h[3], pa_l[3]);

            uint32_t v_h[8][2], v_l[8][2];
            const int srow = j*16 + (lane & 15);
            #pragma unroll
            for (int np = 0; np < 4; np++) {
                const uint32_t off = SWZ((uint32_t)(srow*128 + np*32 + ((lane >> 4) & 1)*16));
                uint32_t r0, r1, r2, r3;
                ldsm4t(r0, r1, r2, r3, st + 16384 + off);
                v_h[np*2][0] = r0; v_h[np*2][1] = r1;
                v_h[np*2+1][0] = r2; v_h[np*2+1][1] = r3;
                ldsm4t(r0, r1, r2, r3, st + 24576 + off);
                v_l[np*2][0] = r0; v_l[np*2][1] = r1;
                v_l[np*2+1][0] = r2; v_l[np*2+1][1] = r3;
            }
            #pragma unroll
            for (int nt = 0; nt < 8; nt++) {
                mma_bf16(oacc[nt], pa_h, v_h[nt]);
                mma_bf16(oacc[nt], pa_h, v_l[nt]);
                mma_bf16(oacc[nt], pa_l, v_h[nt]);
            }
        }
        __syncthreads();
        if (kt + 2 < ntiles) load_kv(kt + 2, kt & 1);
    }

    const float inv0 = 1.f / l0, inv1 = 1.f / l1;
    const int rr = lane >> 2, cc = (lane & 3)*2;
    const size_t row0 = bo + qt*64 + wid*16 + rr;
    #pragma unroll
    for (int nt = 0; nt < 8; nt++) {
        const int col = head*64 + nt*8 + cc;
        uint32_t hi, lo;
        split_pack(oacc[nt][0]*inv0, oacc[nt][1]*inv0, hi, lo);
        *reinterpret_cast<uint32_t*>(&Oh[row0*ors + col]) = hi;
        *reinterpret_cast<uint32_t*>(&Ol[row0*ors + col]) = lo;
        split_pack(oacc[nt][2]*inv1, oacc[nt][3]*inv1, hi, lo);
        *reinterpret_cast<uint32_t*>(&Oh[(row0+8)*ors + col]) = hi;
        *reinterpret_cast<uint32_t*>(&Ol[(row0+8)*ors + col]) = lo;
    }
}

// ---------------- launch ----------------
extern "C" void kernel_launch(void* const* d_in, const int* in_sizes, int n_in,
                              void* d_out, int out_size)
{
    const float* x         = (const float*)d_in[0];
    const float* pos_emb   = (const float*)d_in[1];
    const float* l_q_w     = (const float*)d_in[2];
    const float* l_kv_w    = (const float*)d_in[3];
    const float* l_proj_w  = (const float*)d_in[4];
    const float* l_proj_b  = (const float*)d_in[5];
    const float* h_qkv_w   = (const float*)d_in[6];
    const float* h_proj_w  = (const float*)d_in[7];
    const float* h_proj_b  = (const float*)d_in[8];
    const float* in_proj_w = (const float*)d_in[9];
    const float* in_proj_b = (const float*)d_in[10];
    const float* out_proj_w= (const float*)d_in[11];
    const float* out_proj_b= (const float*)d_in[12];
    float* out = (float*)d_out;

    __nv_bfloat16 *cth,*ctl,*xph,*xpl,*qmh,*qml;
    __nv_bfloat16 *hh,*hl,*lh,*ll,*yh,*yl,*mh,*ml;
    __nv_bfloat16 *wch,*wcl,*w3h,*w3l,*w4h,*w4l,*w5h,*w5l,*w6h,*w6l;
    cudaGetSymbolAddress((void**)&cth, g_cat_h);  cudaGetSymbolAddress((void**)&ctl, g_cat_l);
    cudaGetSymbolAddress((void**)&xph, g_xp_h);   cudaGetSymbolAddress((void**)&xpl, g_xp_l);
    cudaGetSymbolAddress((void**)&qmh, g_qm_h);   cudaGetSymbolAddress((void**)&qml, g_qm_l);
    cudaGetSymbolAddress((void**)&hh,  g_hifi_h); cudaGetSymbolAddress((void**)&hl,  g_hifi_l);
    cudaGetSymbolAddress((void**)&lh,  g_lofi_h); cudaGetSymbolAddress((void**)&ll,  g_lofi_l);
    cudaGetSymbolAddress((void**)&yh,  g_y_h);    cudaGetSymbolAddress((void**)&yl,  g_y_l);
    cudaGetSymbolAddress((void**)&mh,  g_mha_h);  cudaGetSymbolAddress((void**)&ml,  g_mha_l);
    cudaGetSymbolAddress((void**)&wch, g_wch);    cudaGetSymbolAddress((void**)&wcl, g_wcl);
    cudaGetSymbolAddress((void**)&w3h, g_w3h);    cudaGetSymbolAddress((void**)&w3l, g_w3l);
    cudaGetSymbolAddress((void**)&w4h, g_w4h);    cudaGetSymbolAddress((void**)&w4l, g_w4l);
    cudaGetSymbolAddress((void**)&w5h, g_w5h);    cudaGetSymbolAddress((void**)&w5l, g_w5l);
    cudaGetSymbolAddress((void**)&w6h, g_w6h);    cudaGetSymbolAddress((void**)&w6l, g_w6l);

    cudaFuncSetAttribute(gemm_mma_kernel,      cudaFuncAttributeMaxDynamicSharedMemorySize, GEMM_SMEM);
    cudaFuncSetAttribute(gemm_mma_dual_kernel, cudaFuncAttributeMaxDynamicSharedMemorySize, GEMM_SMEM);
    cudaFuncSetAttribute(flash_mma_kernel,     cudaFuncAttributeMaxDynamicSharedMemorySize, FLASH_SMEM);

    const int M = MTOT;
    const dim3 wb(32, 8);

    // launch order places catGEMM at index 5 for ncu (-s 5 -c 1)
    add_pos_split_kernel<<<(M*CDIM/4 + 255)/256, 256>>>(x, pos_emb, xph, xpl);                     // 0
    wsplit_kernel<<<dim3(768/32, 512/32),  wb>>>(h_qkv_w, wch,            wcl,            512, 768); // 1
    wsplit_kernel<<<dim3(256/32, 512/32),  wb>>>(l_q_w,   wch + 768*512,  wcl + 768*512,  512, 256); // 2
    wsplit_kernel<<<dim3(512/32, 512/32),  wb>>>(l_kv_w,  wch + 1024*512, wcl + 1024*512, 512, 512); // 3
    wsplit_kernel<<<dim3(1536/32, 512/32), wb>>>(in_proj_w, w5h, w5l, 512, 1536);                    // 4

    // 5: merged input projection (PROFILED)
    gemm_mma_kernel<<<dim3(1536/64, M/128), 256, GEMM_SMEM>>>(
        xph, xpl, wch, wcl, nullptr, nullptr, cth, ctl, 1536, 512, 1536);

    // 6-7: attention branches
    hifi_attn_kernel<<<4096, 128>>>(cth, ctl, hh, hl);
    flash_mma_kernel<<<dim3(SEQ/64, 4, BATCH), 128, FLASH_SMEM>>>(
        cth + 768, ctl + 768, cth + 1024, ctl + 1024, cth + 1280, ctl + 1280,
        lh, ll, 1536, 1536, 256, SEQ);

    // 8-10: remaining weight splits
    wsplit_kernel<<<dim3(256/32, 256/32), wb>>>(h_proj_w,  w3h, w3l, 256, 256);
    wsplit_kernel<<<dim3(256/32, 256/32), wb>>>(l_proj_w,  w4h, w4l, 256, 256);
    wsplit_kernel<<<dim3(512/32, 512/32), wb>>>(out_proj_w,w6h, w6l, 512, 512);

    // 11: h_proj + l_proj fused in one launch -> split y
    gemm_mma_dual_kernel<<<dim3(256/64, M/128, 2), 256, GEMM_SMEM>>>(
        hh, hl, w3h, w3l, h_proj_b, yh,       yl,
        lh, ll, w4h, w4l, l_proj_b, yh + 256, yl + 256,
        256, 256, 512);

    // 12-14: final MHA
    gemm_mma_kernel<<<dim3(1536/64, M/128), 256, GEMM_SMEM>>>(
        yh, yl, w5h, w5l, in_proj_b, nullptr, qmh, qml, 1536, 512, 1536);
    flash_mma_kernel<<<dim3(SEQ/64, 8, BATCH), 128, FLASH_SMEM>>>(
        qmh, qml, qmh + 512, qml + 512, qmh + 1024, qml + 1024, mh, ml, 1536, 1536, 512, SEQ);
    gemm_mma_kernel<<<dim3(512/64, M/128), 256, GEMM_SMEM>>>(
        mh, ml, w6h, w6l, out_proj_b, out, nullptr, nullptr, 512, 512, 512);
}